// round 8
// baseline (speedup 1.0000x reference)
#include <cuda_runtime.h>
#include <cuda_bf16.h>
#include <stdint.h>

// Problem constants
#define BATCH 4
#define SEQ   2048
#define DIM   1024
#define NHEAD 16
#define HDIM  64
#define WIN   256
#define MROWS (BATCH * SEQ)   // 8192

// ---------------------------------------------------------------------------
// Scratch (device globals: allocation-free rule)
// ---------------------------------------------------------------------------
__device__ __nv_bfloat16 g_qh[MROWS * DIM];
__device__ __nv_bfloat16 g_ql[MROWS * DIM];
__device__ __nv_bfloat16 g_kh[MROWS * DIM];
__device__ __nv_bfloat16 g_kl[MROWS * DIM];
__device__ __nv_bfloat16 g_vh[MROWS * DIM];
__device__ __nv_bfloat16 g_vl[MROWS * DIM];
__device__ __nv_bfloat16 g_xh[MROWS * DIM];
__device__ __nv_bfloat16 g_xl[MROWS * DIM];
__device__ __nv_bfloat16 g_ch[MROWS * DIM];
__device__ __nv_bfloat16 g_cl[MROWS * DIM];
__device__ __nv_bfloat16 g_wqh[DIM * DIM];
__device__ __nv_bfloat16 g_wql[DIM * DIM];
__device__ __nv_bfloat16 g_wkh[DIM * DIM];
__device__ __nv_bfloat16 g_wkl[DIM * DIM];
__device__ __nv_bfloat16 g_wvh[DIM * DIM];
__device__ __nv_bfloat16 g_wvl[DIM * DIM];
__device__ __nv_bfloat16 g_woh[DIM * DIM];
__device__ __nv_bfloat16 g_wol[DIM * DIM];

// ---------------------------------------------------------------------------
// Portable PTX helpers
// ---------------------------------------------------------------------------
__device__ __forceinline__ uint32_t smem_u32(const void* p) {
    uint32_t a;
    asm("{ .reg .u64 t; cvta.to.shared.u64 t, %1; cvt.u32.u64 %0, t; }"
        : "=r"(a) : "l"(p));
    return a;
}

#define CP_ASYNC16(dst, src) \
    asm volatile("cp.async.cg.shared.global [%0], [%1], 16;" :: "r"(dst), "l"(src))
#define CP_COMMIT() asm volatile("cp.async.commit_group;" ::: "memory")
#define CP_WAIT(n)  asm volatile("cp.async.wait_group %0;" :: "n"(n) : "memory")

__device__ __forceinline__ void ldsm_x4(uint32_t& r0, uint32_t& r1,
                                        uint32_t& r2, uint32_t& r3, uint32_t addr) {
    asm volatile("ldmatrix.sync.aligned.m8n8.x4.shared.b16 {%0,%1,%2,%3}, [%4];"
                 : "=r"(r0), "=r"(r1), "=r"(r2), "=r"(r3) : "r"(addr));
}

__device__ __forceinline__ void ldsm_x4_t(uint32_t& r0, uint32_t& r1,
                                          uint32_t& r2, uint32_t& r3, uint32_t addr) {
    asm volatile("ldmatrix.sync.aligned.m8n8.x4.trans.shared.b16 {%0,%1,%2,%3}, [%4];"
                 : "=r"(r0), "=r"(r1), "=r"(r2), "=r"(r3) : "r"(addr));
}

__device__ __forceinline__ void mma_bf16(float& c0, float& c1, float& c2, float& c3,
                                         uint32_t a0, uint32_t a1, uint32_t a2, uint32_t a3,
                                         uint32_t b0, uint32_t b1) {
    asm volatile(
        "mma.sync.aligned.m16n8k16.row.col.f32.bf16.bf16.f32 "
        "{%0,%1,%2,%3}, {%4,%5,%6,%7}, {%8,%9}, {%0,%1,%2,%3};"
        : "+f"(c0), "+f"(c1), "+f"(c2), "+f"(c3)
        : "r"(a0), "r"(a1), "r"(a2), "r"(a3), "r"(b0), "r"(b1));
}

__device__ __forceinline__ uint32_t pack_bf2(__nv_bfloat16 a, __nv_bfloat16 b) {
    __nv_bfloat162 t(a, b);
    return *(uint32_t*)&t;
}

__device__ __forceinline__ void split2(float a, float b, uint32_t& hi, uint32_t& lo) {
    __nv_bfloat16 ha = __float2bfloat16(a), hb = __float2bfloat16(b);
    float ra = a - __bfloat162float(ha);
    float rb = b - __bfloat162float(hb);
    hi = pack_bf2(ha, hb);
    lo = pack_bf2(__float2bfloat16(ra), __float2bfloat16(rb));
}

// ---------------------------------------------------------------------------
// fp32 -> bf16 hi/lo splits
// ---------------------------------------------------------------------------
__global__ __launch_bounds__(256) void split_bf16(const float* __restrict__ src,
                                                  __nv_bfloat16* __restrict__ hi,
                                                  __nv_bfloat16* __restrict__ lo,
                                                  int n) {
    int i = (blockIdx.x * 256 + threadIdx.x) * 4;
    if (i >= n) return;
    float4 x = *(const float4*)(src + i);
    uint32_t h0, l0, h1, l1;
    split2(x.x, x.y, h0, l0);
    split2(x.z, x.w, h1, l1);
    uint32_t* ph = (uint32_t*)(hi + i);
    uint32_t* pl = (uint32_t*)(lo + i);
    ph[0] = h0; ph[1] = h1;
    pl[0] = l0; pl[1] = l1;
}

// all 4 weight matrices in one launch; blockIdx.y selects the tensor
__global__ __launch_bounds__(256) void split_w4(const float* __restrict__ s0,
                                                const float* __restrict__ s1,
                                                const float* __restrict__ s2,
                                                const float* __restrict__ s3,
                                                __nv_bfloat16* __restrict__ h0,
                                                __nv_bfloat16* __restrict__ l0p,
                                                __nv_bfloat16* __restrict__ h1,
                                                __nv_bfloat16* __restrict__ l1p,
                                                __nv_bfloat16* __restrict__ h2,
                                                __nv_bfloat16* __restrict__ l2p,
                                                __nv_bfloat16* __restrict__ h3,
                                                __nv_bfloat16* __restrict__ l3p) {
    int w = blockIdx.y;
    const float* src = (w == 0) ? s0 : (w == 1) ? s1 : (w == 2) ? s2 : s3;
    __nv_bfloat16* hi = (w == 0) ? h0 : (w == 1) ? h1 : (w == 2) ? h2 : h3;
    __nv_bfloat16* lo = (w == 0) ? l0p : (w == 1) ? l1p : (w == 2) ? l2p : l3p;
    int i = (blockIdx.x * 256 + threadIdx.x) * 4;
    float4 x = *(const float4*)(src + i);
    uint32_t a0, b0, a1, b1;
    split2(x.x, x.y, a0, b0);
    split2(x.z, x.w, a1, b1);
    uint32_t* ph = (uint32_t*)(hi + i);
    uint32_t* pl = (uint32_t*)(lo + i);
    ph[0] = a0; ph[1] = a1;
    pl[0] = b0; pl[1] = b1;
}

// ---------------------------------------------------------------------------
// HMMA bf16-split GEMM core (fragment maps verified R3/R4)
// ---------------------------------------------------------------------------
#define GP      40
#define TBYTES  (128 * GP * 2)
#define STAGEB  (4 * TBYTES)
#define NCH     (DIM / 32)

template <bool BF16OUT>
__device__ __forceinline__ void gemm_body(const __nv_bfloat16* Ah, const __nv_bfloat16* Al,
                                          const __nv_bfloat16* Bh, const __nv_bfloat16* Bl,
                                          const float* bias, float* C,
                                          __nv_bfloat16* Ch, __nv_bfloat16* Cl,
                                          int bm, int bn, char* smem) {
    const int tid = threadIdx.x;
    const int wid = tid >> 5;
    const int lane = tid & 31;
    const int wm = (wid & 1) * 64;
    const int wn = (wid >> 1) * 32;
    const uint32_t sbase = smem_u32(smem);

    const char* gAh = (const char*)Ah + (size_t)bm * (DIM * 2);
    const char* gAl = (const char*)Al + (size_t)bm * (DIM * 2);
    const char* gBh = (const char*)Bh + (size_t)bn * (DIM * 2);
    const char* gBl = (const char*)Bl + (size_t)bn * (DIM * 2);

    auto issue = [&](int c, int s) {
        char* st = smem + s * STAGEB;
        const size_t gk = (size_t)c * 64;
#pragma unroll
        for (int rep = 0; rep < 2; rep++) {
            int t = rep ? (tid + 256) : tid;
            int r = t >> 2;
            int cc = (t & 3) << 4;
            uint32_t dst = smem_u32(st) + r * 80 + cc;
            size_t src = (size_t)r * (DIM * 2) + gk + cc;
            CP_ASYNC16(dst,              gAh + src);
            CP_ASYNC16(dst + TBYTES,     gAl + src);
            CP_ASYNC16(dst + 2 * TBYTES, gBh + src);
            CP_ASYNC16(dst + 3 * TBYTES, gBl + src);
        }
    };

    float acc[4][4][4];
#pragma unroll
    for (int i = 0; i < 4; i++)
#pragma unroll
        for (int j = 0; j < 4; j++)
#pragma unroll
            for (int r = 0; r < 4; r++) acc[i][j][r] = 0.0f;

    const int a_r = lane & 15, a_c = (lane >> 4) * 8;
    const int b_r = (lane & 7) + ((lane >> 4) & 1) * 8, b_c = ((lane >> 3) & 1) * 8;

    issue(0, 0);
    CP_COMMIT();

    for (int c = 0; c < NCH; ++c) {
        const int s = c & 1;
        if (c + 1 < NCH) {
            issue(c + 1, s ^ 1);
            CP_COMMIT();
            CP_WAIT(1);
        } else {
            CP_WAIT(0);
        }
        __syncthreads();

        const uint32_t st = sbase + s * STAGEB;
        const uint32_t pAh = st;
        const uint32_t pAl = st + TBYTES;
        const uint32_t pBh = st + 2 * TBYTES;
        const uint32_t pBl = st + 3 * TBYTES;

#pragma unroll
        for (int kk = 0; kk < 32; kk += 16) {
            uint32_t ah[4][4], al[4][4];
#pragma unroll
            for (int mi = 0; mi < 4; mi++) {
                uint32_t off = (uint32_t)((wm + mi * 16 + a_r) * 80 + (kk + a_c) * 2);
                ldsm_x4(ah[mi][0], ah[mi][1], ah[mi][2], ah[mi][3], pAh + off);
                ldsm_x4(al[mi][0], al[mi][1], al[mi][2], al[mi][3], pAl + off);
            }
            uint32_t bh[4][2], bl[4][2];
#pragma unroll
            for (int nb = 0; nb < 2; nb++) {
                uint32_t off = (uint32_t)((wn + nb * 16 + b_r) * 80 + (kk + b_c) * 2);
                uint32_t r0, r1, r2, r3;
                ldsm_x4(r0, r1, r2, r3, pBh + off);
                bh[nb * 2][0] = r0; bh[nb * 2][1] = r1;
                bh[nb * 2 + 1][0] = r2; bh[nb * 2 + 1][1] = r3;
                ldsm_x4(r0, r1, r2, r3, pBl + off);
                bl[nb * 2][0] = r0; bl[nb * 2][1] = r1;
                bl[nb * 2 + 1][0] = r2; bl[nb * 2 + 1][1] = r3;
            }
#pragma unroll
            for (int mi = 0; mi < 4; mi++)
#pragma unroll
                for (int ni = 0; ni < 4; ni++) {
                    mma_bf16(acc[mi][ni][0], acc[mi][ni][1], acc[mi][ni][2], acc[mi][ni][3],
                             ah[mi][0], ah[mi][1], ah[mi][2], ah[mi][3],
                             bh[ni][0], bh[ni][1]);
                    mma_bf16(acc[mi][ni][0], acc[mi][ni][1], acc[mi][ni][2], acc[mi][ni][3],
                             ah[mi][0], ah[mi][1], ah[mi][2], ah[mi][3],
                             bl[ni][0], bl[ni][1]);
                    mma_bf16(acc[mi][ni][0], acc[mi][ni][1], acc[mi][ni][2], acc[mi][ni][3],
                             al[mi][0], al[mi][1], al[mi][2], al[mi][3],
                             bh[ni][0], bh[ni][1]);
                }
        }
        __syncthreads();
    }

    const int er = lane >> 2;
    const int ec = (lane & 3) * 2;
#pragma unroll
    for (int mi = 0; mi < 4; mi++) {
#pragma unroll
        for (int ni = 0; ni < 4; ni++) {
            int col = bn + wn + ni * 8 + ec;
            int row0 = bm + wm + mi * 16 + er;
            int row1 = row0 + 8;
            if (BF16OUT) {
                uint32_t h0, l0, h1, l1;
                split2(acc[mi][ni][0], acc[mi][ni][1], h0, l0);
                split2(acc[mi][ni][2], acc[mi][ni][3], h1, l1);
                *(uint32_t*)(Ch + (size_t)row0 * DIM + col) = h0;
                *(uint32_t*)(Cl + (size_t)row0 * DIM + col) = l0;
                *(uint32_t*)(Ch + (size_t)row1 * DIM + col) = h1;
                *(uint32_t*)(Cl + (size_t)row1 * DIM + col) = l1;
            } else {
                float b0 = bias[col], b1 = bias[col + 1];
                *(float2*)(C + (size_t)row0 * DIM + col) =
                    make_float2(acc[mi][ni][0] + b0, acc[mi][ni][1] + b1);
                *(float2*)(C + (size_t)row1 * DIM + col) =
                    make_float2(acc[mi][ni][2] + b0, acc[mi][ni][3] + b1);
            }
        }
    }
}

__global__ __launch_bounds__(256) void gemm_qkv(const __nv_bfloat16* __restrict__ xh,
                                                const __nv_bfloat16* __restrict__ xl,
                                                const __nv_bfloat16* __restrict__ wqh,
                                                const __nv_bfloat16* __restrict__ wql,
                                                const __nv_bfloat16* __restrict__ wkh,
                                                const __nv_bfloat16* __restrict__ wkl,
                                                const __nv_bfloat16* __restrict__ wvh,
                                                const __nv_bfloat16* __restrict__ wvl,
                                                __nv_bfloat16* __restrict__ qh,
                                                __nv_bfloat16* __restrict__ ql,
                                                __nv_bfloat16* __restrict__ kh,
                                                __nv_bfloat16* __restrict__ kl,
                                                __nv_bfloat16* __restrict__ vh,
                                                __nv_bfloat16* __restrict__ vl) {
    extern __shared__ char smem[];
    const __nv_bfloat16* bh = (blockIdx.z == 0) ? wqh : (blockIdx.z == 1) ? wkh : wvh;
    const __nv_bfloat16* bl = (blockIdx.z == 0) ? wql : (blockIdx.z == 1) ? wkl : wvl;
    __nv_bfloat16* oh = (blockIdx.z == 0) ? qh : (blockIdx.z == 1) ? kh : vh;
    __nv_bfloat16* ol = (blockIdx.z == 0) ? ql : (blockIdx.z == 1) ? kl : vl;
    gemm_body<true>(xh, xl, bh, bl, nullptr, nullptr, oh, ol,
                    blockIdx.y * 128, blockIdx.x * 128, smem);
}

__global__ __launch_bounds__(256) void gemm_out(const __nv_bfloat16* __restrict__ ah,
                                                const __nv_bfloat16* __restrict__ al,
                                                const __nv_bfloat16* __restrict__ bh,
                                                const __nv_bfloat16* __restrict__ bl,
                                                const float* __restrict__ bias,
                                                float* __restrict__ C) {
    extern __shared__ char smem[];
    gemm_body<false>(ah, al, bh, bl, bias, C, nullptr, nullptr,
                     blockIdx.y * 128, blockIdx.x * 128, smem);
}

// ---------------------------------------------------------------------------
// HMMA windowed flash attention, bf16 hi/lo inputs.
// Block: 128 threads (4 warps), 64 queries. Tiles 64 rows x 128B, pitch 144B.
// smem arena: 8 tiles (73728B). Q uses tiles 0-1 only during fragment preload,
// then the same space becomes KV double-buffer stage 0 (tiles 0-3) / stage 1
// (tiles 4-7). 3 CTAs/SM.
// ---------------------------------------------------------------------------
#define APITCH 144
#define ATB    (64 * APITCH)        // 9216 bytes per tile
#define ADYN   (8 * ATB)            // 73728

__global__ __launch_bounds__(128, 3) void attn_mma(const __nv_bfloat16* __restrict__ Qh,
                                                   const __nv_bfloat16* __restrict__ Ql,
                                                   const __nv_bfloat16* __restrict__ Kh,
                                                   const __nv_bfloat16* __restrict__ Kl,
                                                   const __nv_bfloat16* __restrict__ Vh,
                                                   const __nv_bfloat16* __restrict__ Vl,
                                                   __nv_bfloat16* __restrict__ ch,
                                                   __nv_bfloat16* __restrict__ cl) {
    extern __shared__ char smem[];
    const uint32_t s0 = smem_u32(smem);

    const int qb = blockIdx.x * 64;
    const int h = blockIdx.y;
    const int b = blockIdx.z;
    const int tid = threadIdx.x;
    const int warp = tid >> 5;
    const int lane = tid & 31;

    // ---- Phase 1: Q tile -> smem tiles 0,1 -> register fragments ----
    {
        const char* gQh = (const char*)Qh + (((size_t)b * SEQ + qb) * DIM + h * HDIM) * 2;
        const char* gQl = (const char*)Ql + (((size_t)b * SEQ + qb) * DIM + h * HDIM) * 2;
        for (int i = tid; i < 512; i += 128) {
            int r = i >> 3;
            int c = (i & 7) << 4;
            uint32_t dst = s0 + r * APITCH + c;
            size_t src = (size_t)r * (DIM * 2) + c;
            CP_ASYNC16(dst, gQh + src);
            CP_ASYNC16(dst + ATB, gQl + src);
        }
        CP_COMMIT();
        CP_WAIT(0);
        __syncthreads();
    }

    const int a_r = lane & 15, a_c = (lane >> 4) * 8;
    const int b_r = (lane & 7) + ((lane >> 4) & 1) * 8, b_c = ((lane >> 3) & 1) * 8;
    const int v_r = (lane & 7) + ((lane >> 3) & 1) * 8, v_c = ((lane >> 4) & 1) * 8;

    uint32_t qfh[4][4], qfl[4][4];
#pragma unroll
    for (int t = 0; t < 4; t++) {
        uint32_t off = (uint32_t)((warp * 16 + a_r) * APITCH + (t * 16 + a_c) * 2);
        ldsm_x4(qfh[t][0], qfh[t][1], qfh[t][2], qfh[t][3], s0 + off);
        ldsm_x4(qfl[t][0], qfl[t][1], qfl[t][2], qfl[t][3], s0 + ATB + off);
    }
    __syncthreads();   // Q smem fully consumed; arena now belongs to the KV pipeline

    // ---- Phase 2: KV double-buffered mainloop ----
    int kstart = qb - (WIN - 1);
    if (kstart < 0) kstart = 0;
    kstart &= ~63;
    const int ntiles = (qb + 63 - kstart) / 64 + 1;

    auto issueKV = [&](int kt, int s) {
        const size_t base = (((size_t)b * SEQ + kt) * DIM + h * HDIM) * 2;
        const char* pKh = (const char*)Kh + base;
        const char* pKl = (const char*)Kl + base;
        const char* pVh = (const char*)Vh + base;
        const char* pVl = (const char*)Vl + base;
        uint32_t sb = s0 + s * 4 * ATB;
        for (int i = tid; i < 512; i += 128) {
            int r = i >> 3;
            int c = (i & 7) << 4;
            uint32_t dst = sb + r * APITCH + c;
            size_t src = (size_t)r * (DIM * 2) + c;
            CP_ASYNC16(dst,           pKh + src);
            CP_ASYNC16(dst + ATB,     pKl + src);
            CP_ASYNC16(dst + 2 * ATB, pVh + src);
            CP_ASYNC16(dst + 3 * ATB, pVl + src);
        }
    };

    issueKV(kstart, 0);
    CP_COMMIT();
    if (ntiles > 1) {
        issueKV(kstart + 64, 1);
        CP_COMMIT();
    }

    float m0 = -1e30f, m1 = -1e30f, l0 = 0.0f, l1 = 0.0f;
    float o[8][4];
#pragma unroll
    for (int j = 0; j < 8; j++)
#pragma unroll
        for (int r = 0; r < 4; r++) o[j][r] = 0.0f;

    const int row0 = qb + warp * 16 + (lane >> 2);
    const int row1 = row0 + 8;

    for (int it = 0; it < ntiles; ++it) {
        const int kt = kstart + it * 64;
        const int s = it & 1;
        if (it + 1 < ntiles) { CP_WAIT(1); } else { CP_WAIT(0); }
        __syncthreads();

        const uint32_t sKh = s0 + s * 4 * ATB;
        const uint32_t sKl = sKh + ATB;
        const uint32_t sVh = sKh + 2 * ATB;
        const uint32_t sVl = sKh + 3 * ATB;

        // ---- scores S = Q K^T (3-pass) ----
        float acc[8][4];
#pragma unroll
        for (int j = 0; j < 8; j++)
#pragma unroll
            for (int r = 0; r < 4; r++) acc[j][r] = 0.0f;

#pragma unroll
        for (int t = 0; t < 4; t++) {
#pragma unroll
            for (int g = 0; g < 4; g++) {
                uint32_t off = (uint32_t)((g * 16 + b_r) * APITCH + (t * 16 + b_c) * 2);
                uint32_t kh0, kh1, kh2, kh3, kl0, kl1, kl2, kl3;
                ldsm_x4(kh0, kh1, kh2, kh3, sKh + off);
                ldsm_x4(kl0, kl1, kl2, kl3, sKl + off);
                int n0 = 2 * g, n1 = 2 * g + 1;
                mma_bf16(acc[n0][0], acc[n0][1], acc[n0][2], acc[n0][3],
                         qfh[t][0], qfh[t][1], qfh[t][2], qfh[t][3], kh0, kh1);
                mma_bf16(acc[n1][0], acc[n1][1], acc[n1][2], acc[n1][3],
                         qfh[t][0], qfh[t][1], qfh[t][2], qfh[t][3], kh2, kh3);
                mma_bf16(acc[n0][0], acc[n0][1], acc[n0][2], acc[n0][3],
                         qfh[t][0], qfh[t][1], qfh[t][2], qfh[t][3], kl0, kl1);
                mma_bf16(acc[n1][0], acc[n1][1], acc[n1][2], acc[n1][3],
                         qfh[t][0], qfh[t][1], qfh[t][2], qfh[t][3], kl2, kl3);
                mma_bf16(acc[n0][0], acc[n0][1], acc[n0][2], acc[n0][3],
                         qfl[t][0], qfl[t][1], qfl[t][2], qfl[t][3], kh0, kh1);
                mma_bf16(acc[n1][0], acc[n1][1], acc[n1][2], acc[n1][3],
                         qfl[t][0], qfl[t][1], qfl[t][2], qfl[t][3], kh2, kh3);
            }
        }

        // ---- mask + online softmax ----
        float tmax0 = -1e30f, tmax1 = -1e30f;
#pragma unroll
        for (int j = 0; j < 8; j++) {
            int colb = kt + 8 * j + 2 * (lane & 3);
#pragma unroll
            for (int e = 0; e < 2; e++) {
                int col = colb + e;
                bool v0 = (col <= row0) && (row0 - col < WIN);
                bool v1 = (col <= row1) && (row1 - col < WIN);
                if (!v0) acc[j][e] = -1e30f;
                if (!v1) acc[j][2 + e] = -1e30f;
            }
            tmax0 = fmaxf(tmax0, fmaxf(acc[j][0], acc[j][1]));
            tmax1 = fmaxf(tmax1, fmaxf(acc[j][2], acc[j][3]));
        }
#pragma unroll
        for (int off = 1; off <= 2; off <<= 1) {
            tmax0 = fmaxf(tmax0, __shfl_xor_sync(0xffffffffu, tmax0, off));
            tmax1 = fmaxf(tmax1, __shfl_xor_sync(0xffffffffu, tmax1, off));
        }
        float mn0 = fmaxf(m0, tmax0);
        float mn1 = fmaxf(m1, tmax1);

        float rs0 = 0.0f, rs1 = 0.0f;
#pragma unroll
        for (int j = 0; j < 8; j++) {
            acc[j][0] = __expf(acc[j][0] - mn0);
            acc[j][1] = __expf(acc[j][1] - mn0);
            acc[j][2] = __expf(acc[j][2] - mn1);
            acc[j][3] = __expf(acc[j][3] - mn1);
            rs0 += acc[j][0] + acc[j][1];
            rs1 += acc[j][2] + acc[j][3];
        }
#pragma unroll
        for (int off = 1; off <= 2; off <<= 1) {
            rs0 += __shfl_xor_sync(0xffffffffu, rs0, off);
            rs1 += __shfl_xor_sync(0xffffffffu, rs1, off);
        }
        float corr0 = __expf(m0 - mn0);
        float corr1 = __expf(m1 - mn1);
        l0 = l0 * corr0 + rs0;
        l1 = l1 * corr1 + rs1;
        m0 = mn0;
        m1 = mn1;
#pragma unroll
        for (int j = 0; j < 8; j++) {
            o[j][0] *= corr0;
            o[j][1] *= corr0;
            o[j][2] *= corr1;
            o[j][3] *= corr1;
        }

        // ---- O += P V (3-pass, P from registers; V via ldmatrix.trans) ----
#pragma unroll
        for (int t = 0; t < 4; t++) {
            uint32_t ph[4], pl[4];
            split2(acc[2 * t][0], acc[2 * t][1], ph[0], pl[0]);
            split2(acc[2 * t][2], acc[2 * t][3], ph[1], pl[1]);
            split2(acc[2 * t + 1][0], acc[2 * t + 1][1], ph[2], pl[2]);
            split2(acc[2 * t + 1][2], acc[2 * t + 1][3], ph[3], pl[3]);
#pragma unroll
            for (int g = 0; g < 4; g++) {
                uint32_t off = (uint32_t)((t * 16 + v_r) * APITCH + (g * 16 + v_c) * 2);
                uint32_t vh0, vh1, vh2, vh3, vl0, vl1, vl2, vl3;
                ldsm_x4_t(vh0, vh1, vh2, vh3, sVh + off);
                ldsm_x4_t(vl0, vl1, vl2, vl3, sVl + off);
                int n0 = 2 * g, n1 = 2 * g + 1;
                mma_bf16(o[n0][0], o[n0][1], o[n0][2], o[n0][3],
                         ph[0], ph[1], ph[2], ph[3], vh0, vh1);
                mma_bf16(o[n1][0], o[n1][1], o[n1][2], o[n1][3],
                         ph[0], ph[1], ph[2], ph[3], vh2, vh3);
                mma_bf16(o[n0][0], o[n0][1], o[n0][2], o[n0][3],
                         ph[0], ph[1], ph[2], ph[3], vl0, vl1);
                mma_bf16(o[n1][0], o[n1][1], o[n1][2], o[n1][3],
                         ph[0], ph[1], ph[2], ph[3], vl2, vl3);
                mma_bf16(o[n0][0], o[n0][1], o[n0][2], o[n0][3],
                         pl[0], pl[1], pl[2], pl[3], vh0, vh1);
                mma_bf16(o[n1][0], o[n1][1], o[n1][2], o[n1][3],
                         pl[0], pl[1], pl[2], pl[3], vh2, vh3);
            }
        }
        __syncthreads();   // stage s fully read
        if (it + 2 < ntiles) {
            issueKV(kstart + (it + 2) * 64, s);
            CP_COMMIT();
        }
    }

    // ---- epilogue: normalize, split to bf16 hi/lo ctx ----
    float inv0 = 1.0f / l0;
    float inv1 = 1.0f / l1;
    const size_t tok0 = (size_t)b * SEQ + row0;
    const size_t tok1 = (size_t)b * SEQ + row1;
    const int colbase = h * HDIM + 2 * (lane & 3);
#pragma unroll
    for (int j = 0; j < 8; j++) {
        int col = colbase + 8 * j;
        uint32_t h0, lo0, h1, lo1;
        split2(o[j][0] * inv0, o[j][1] * inv0, h0, lo0);
        split2(o[j][2] * inv1, o[j][3] * inv1, h1, lo1);
        *(uint32_t*)(ch + tok0 * DIM + col) = h0;
        *(uint32_t*)(cl + tok0 * DIM + col) = lo0;
        *(uint32_t*)(ch + tok1 * DIM + col) = h1;
        *(uint32_t*)(cl + tok1 * DIM + col) = lo1;
    }
}

// ---------------------------------------------------------------------------
extern "C" void kernel_launch(void* const* d_in, const int* in_sizes, int n_in,
                              void* d_out, int out_size) {
    (void)in_sizes; (void)n_in; (void)out_size;
    const float* X  = (const float*)d_in[0];
    const float* Wq = (const float*)d_in[1];
    const float* Wk = (const float*)d_in[2];
    const float* Wv = (const float*)d_in[3];
    const float* Wo = (const float*)d_in[4];
    const float* bo = (const float*)d_in[5];
    float* out = (float*)d_out;

    __nv_bfloat16 *qh, *ql, *kh, *kl, *vh, *vl, *xh, *xl, *ch, *cl;
    __nv_bfloat16 *wqh, *wql, *wkh, *wkl, *wvh, *wvl, *woh, *wol;
    cudaGetSymbolAddress((void**)&qh, g_qh);
    cudaGetSymbolAddress((void**)&ql, g_ql);
    cudaGetSymbolAddress((void**)&kh, g_kh);
    cudaGetSymbolAddress((void**)&kl, g_kl);
    cudaGetSymbolAddress((void**)&vh, g_vh);
    cudaGetSymbolAddress((void**)&vl, g_vl);
    cudaGetSymbolAddress((void**)&xh, g_xh);
    cudaGetSymbolAddress((void**)&xl, g_xl);
    cudaGetSymbolAddress((void**)&ch, g_ch);
    cudaGetSymbolAddress((void**)&cl, g_cl);
    cudaGetSymbolAddress((void**)&wqh, g_wqh);
    cudaGetSymbolAddress((void**)&wql, g_wql);
    cudaGetSymbolAddress((void**)&wkh, g_wkh);
    cudaGetSymbolAddress((void**)&wkl, g_wkl);
    cudaGetSymbolAddress((void**)&wvh, g_wvh);
    cudaGetSymbolAddress((void**)&wvl, g_wvl);
    cudaGetSymbolAddress((void**)&woh, g_woh);
    cudaGetSymbolAddress((void**)&wol, g_wol);

    const int DYN = 2 * STAGEB;
    cudaFuncSetAttribute(gemm_qkv, cudaFuncAttributeMaxDynamicSharedMemorySize, DYN);
    cudaFuncSetAttribute(gemm_out, cudaFuncAttributeMaxDynamicSharedMemorySize, DYN);
    cudaFuncSetAttribute(attn_mma, cudaFuncAttributeMaxDynamicSharedMemorySize, ADYN);

    const int nX = MROWS * DIM;
    const int nW = DIM * DIM;

    split_bf16<<<nX / 1024, 256>>>(X, xh, xl, nX);
    dim3 wgrid(nW / 1024, 4);
    split_w4<<<wgrid, 256>>>(Wq, Wk, Wv, Wo,
                             wqh, wql, wkh, wkl, wvh, wvl, woh, wol);

    dim3 qkv_grid(DIM / 128, MROWS / 128, 3);
    gemm_qkv<<<qkv_grid, 256, DYN>>>(xh, xl, wqh, wql, wkh, wkl, wvh, wvl,
                                     qh, ql, kh, kl, vh, vl);

    dim3 attn_grid(SEQ / 64, NHEAD, BATCH);
    attn_mma<<<attn_grid, 128, ADYN>>>(qh, ql, kh, kl, vh, vl, ch, cl);

    dim3 ogrid(DIM / 128, MROWS / 128);
    gemm_out<<<ogrid, 256, DYN>>>(ch, cl, woh, wol, bo, out);
}

// round 10
// speedup vs baseline: 1.1753x; 1.1753x over previous
#include <cuda_runtime.h>
#include <cuda_bf16.h>
#include <cuda_fp16.h>
#include <stdint.h>

// Problem constants
#define BATCH 4
#define SEQ   2048
#define DIM   1024
#define NHEAD 16
#define HDIM  64
#define WIN   256
#define MROWS (BATCH * SEQ)   // 8192

// ---------------------------------------------------------------------------
// Scratch (device globals: allocation-free rule)
// ---------------------------------------------------------------------------
__device__ __nv_bfloat16 g_qh[MROWS * DIM];
__device__ __nv_bfloat16 g_ql[MROWS * DIM];
__device__ __nv_bfloat16 g_kh[MROWS * DIM];
__device__ __nv_bfloat16 g_kl[MROWS * DIM];
__device__ __nv_bfloat16 g_vh[MROWS * DIM];
__device__ __nv_bfloat16 g_vl[MROWS * DIM];
__device__ __nv_bfloat16 g_xh[MROWS * DIM];
__device__ __nv_bfloat16 g_xl[MROWS * DIM];
__device__ __half g_x16[MROWS * DIM];
__device__ __half g_cx16[MROWS * DIM];
__device__ __nv_bfloat16 g_wqh[DIM * DIM];
__device__ __nv_bfloat16 g_wql[DIM * DIM];
__device__ __nv_bfloat16 g_wkh[DIM * DIM];
__device__ __nv_bfloat16 g_wkl[DIM * DIM];
__device__ __half g_wvh16[DIM * DIM];
__device__ __half g_wvl16[DIM * DIM];
__device__ __half g_woh16[DIM * DIM];
__device__ __half g_wol16[DIM * DIM];

// ---------------------------------------------------------------------------
// Portable PTX helpers
// ---------------------------------------------------------------------------
__device__ __forceinline__ uint32_t smem_u32(const void* p) {
    uint32_t a;
    asm("{ .reg .u64 t; cvta.to.shared.u64 t, %1; cvt.u32.u64 %0, t; }"
        : "=r"(a) : "l"(p));
    return a;
}

#define CP_ASYNC16(dst, src) \
    asm volatile("cp.async.cg.shared.global [%0], [%1], 16;" :: "r"(dst), "l"(src))
#define CP_COMMIT() asm volatile("cp.async.commit_group;" ::: "memory")
#define CP_WAIT(n)  asm volatile("cp.async.wait_group %0;" :: "n"(n) : "memory")

__device__ __forceinline__ void ldsm_x4(uint32_t& r0, uint32_t& r1,
                                        uint32_t& r2, uint32_t& r3, uint32_t addr) {
    asm volatile("ldmatrix.sync.aligned.m8n8.x4.shared.b16 {%0,%1,%2,%3}, [%4];"
                 : "=r"(r0), "=r"(r1), "=r"(r2), "=r"(r3) : "r"(addr));
}

__device__ __forceinline__ void ldsm_x4_t(uint32_t& r0, uint32_t& r1,
                                          uint32_t& r2, uint32_t& r3, uint32_t addr) {
    asm volatile("ldmatrix.sync.aligned.m8n8.x4.trans.shared.b16 {%0,%1,%2,%3}, [%4];"
                 : "=r"(r0), "=r"(r1), "=r"(r2), "=r"(r3) : "r"(addr));
}

__device__ __forceinline__ void mma_bf16(float& c0, float& c1, float& c2, float& c3,
                                         uint32_t a0, uint32_t a1, uint32_t a2, uint32_t a3,
                                         uint32_t b0, uint32_t b1) {
    asm volatile(
        "mma.sync.aligned.m16n8k16.row.col.f32.bf16.bf16.f32 "
        "{%0,%1,%2,%3}, {%4,%5,%6,%7}, {%8,%9}, {%0,%1,%2,%3};"
        : "+f"(c0), "+f"(c1), "+f"(c2), "+f"(c3)
        : "r"(a0), "r"(a1), "r"(a2), "r"(a3), "r"(b0), "r"(b1));
}

__device__ __forceinline__ void mma_fp16(float& c0, float& c1, float& c2, float& c3,
                                         uint32_t a0, uint32_t a1, uint32_t a2, uint32_t a3,
                                         uint32_t b0, uint32_t b1) {
    asm volatile(
        "mma.sync.aligned.m16n8k16.row.col.f32.f16.f16.f32 "
        "{%0,%1,%2,%3}, {%4,%5,%6,%7}, {%8,%9}, {%0,%1,%2,%3};"
        : "+f"(c0), "+f"(c1), "+f"(c2), "+f"(c3)
        : "r"(a0), "r"(a1), "r"(a2), "r"(a3), "r"(b0), "r"(b1));
}

__device__ __forceinline__ uint32_t pack_bf2(__nv_bfloat16 a, __nv_bfloat16 b) {
    __nv_bfloat162 t(a, b);
    return *(uint32_t*)&t;
}

__device__ __forceinline__ void split2(float a, float b, uint32_t& hi, uint32_t& lo) {
    __nv_bfloat16 ha = __float2bfloat16(a), hb = __float2bfloat16(b);
    float ra = a - __bfloat162float(ha);
    float rb = b - __bfloat162float(hb);
    hi = pack_bf2(ha, hb);
    lo = pack_bf2(__float2bfloat16(ra), __float2bfloat16(rb));
}

__device__ __forceinline__ uint32_t pack_h2(float a, float b) {
    __half2 t = __floats2half2_rn(a, b);
    return *(uint32_t*)&t;
}

// fp16 hi/lo split of two floats
__device__ __forceinline__ void split2h(float a, float b, uint32_t& hi, uint32_t& lo) {
    __half ha = __float2half_rn(a), hb = __float2half_rn(b);
    float ra = a - __half2float(ha);
    float rb = b - __half2float(hb);
    __half2 th(ha, hb);
    __half2 tl(__float2half_rn(ra), __float2half_rn(rb));
    hi = *(uint32_t*)&th;
    lo = *(uint32_t*)&tl;
}

// ---------------------------------------------------------------------------
// converts
// ---------------------------------------------------------------------------
// X -> bf16 hi/lo (for Q/K proj) AND single fp16 (for V proj)
__global__ __launch_bounds__(256) void split_x(const float* __restrict__ src,
                                               __nv_bfloat16* __restrict__ hi,
                                               __nv_bfloat16* __restrict__ lo,
                                               __half* __restrict__ h16) {
    int i = (blockIdx.x * 256 + threadIdx.x) * 4;
    float4 x = *(const float4*)(src + i);
    uint32_t h0, l0, h1, l1;
    split2(x.x, x.y, h0, l0);
    split2(x.z, x.w, h1, l1);
    uint32_t* ph = (uint32_t*)(hi + i);
    uint32_t* pl = (uint32_t*)(lo + i);
    uint32_t* p16 = (uint32_t*)(h16 + i);
    ph[0] = h0; ph[1] = h1;
    pl[0] = l0; pl[1] = l1;
    p16[0] = pack_h2(x.x, x.y);
    p16[1] = pack_h2(x.z, x.w);
}

// weights: Wq,Wk -> bf16 hi/lo; Wv,Wo -> fp16 hi/lo
__global__ __launch_bounds__(256) void conv_w4(const float* __restrict__ s0,
                                               const float* __restrict__ s1,
                                               const float* __restrict__ s2,
                                               const float* __restrict__ s3,
                                               __nv_bfloat16* __restrict__ bq_h,
                                               __nv_bfloat16* __restrict__ bq_l,
                                               __nv_bfloat16* __restrict__ bk_h,
                                               __nv_bfloat16* __restrict__ bk_l,
                                               __half* __restrict__ hv_h,
                                               __half* __restrict__ hv_l,
                                               __half* __restrict__ ho_h,
                                               __half* __restrict__ ho_l) {
    int w = blockIdx.y;
    int i = (blockIdx.x * 256 + threadIdx.x) * 4;
    if (w < 2) {
        const float* src = (w == 0) ? s0 : s1;
        __nv_bfloat16* hi = (w == 0) ? bq_h : bk_h;
        __nv_bfloat16* lo = (w == 0) ? bq_l : bk_l;
        float4 x = *(const float4*)(src + i);
        uint32_t h0, l0, h1, l1;
        split2(x.x, x.y, h0, l0);
        split2(x.z, x.w, h1, l1);
        uint32_t* ph = (uint32_t*)(hi + i);
        uint32_t* pl = (uint32_t*)(lo + i);
        ph[0] = h0; ph[1] = h1;
        pl[0] = l0; pl[1] = l1;
    } else {
        const float* src = (w == 2) ? s2 : s3;
        __half* hi = (w == 2) ? hv_h : ho_h;
        __half* lo = (w == 2) ? hv_l : ho_l;
        float4 x = *(const float4*)(src + i);
        uint32_t h0, l0, h1, l1;
        split2h(x.x, x.y, h0, l0);
        split2h(x.z, x.w, h1, l1);
        uint32_t* ph = (uint32_t*)(hi + i);
        uint32_t* pl = (uint32_t*)(lo + i);
        ph[0] = h0; ph[1] = h1;
        pl[0] = l0; pl[1] = l1;
    }
}

// ---------------------------------------------------------------------------
// 3-pass bf16 GEMM (verified R3-R8): C = (Ah+Al)(Bh+Bl)^T, bf16 hi/lo out
// ---------------------------------------------------------------------------
#define GP      40
#define TBYTES  (128 * GP * 2)
#define STAGEB  (4 * TBYTES)
#define NCH     (DIM / 32)

__device__ __forceinline__ void gemm3p_body(const __nv_bfloat16* Ah, const __nv_bfloat16* Al,
                                            const __nv_bfloat16* Bh, const __nv_bfloat16* Bl,
                                            __nv_bfloat16* Ch, __nv_bfloat16* Cl,
                                            int bm, int bn, char* smem) {
    const int tid = threadIdx.x;
    const int wid = tid >> 5;
    const int lane = tid & 31;
    const int wm = (wid & 1) * 64;
    const int wn = (wid >> 1) * 32;
    const uint32_t sbase = smem_u32(smem);

    const char* gAh = (const char*)Ah + (size_t)bm * (DIM * 2);
    const char* gAl = (const char*)Al + (size_t)bm * (DIM * 2);
    const char* gBh = (const char*)Bh + (size_t)bn * (DIM * 2);
    const char* gBl = (const char*)Bl + (size_t)bn * (DIM * 2);

    auto issue = [&](int c, int s) {
        uint32_t st = sbase + s * STAGEB;
        const size_t gk = (size_t)c * 64;
#pragma unroll
        for (int rep = 0; rep < 2; rep++) {
            int t = rep ? (tid + 256) : tid;
            int r = t >> 2;
            int cc = (t & 3) << 4;
            uint32_t dst = st + r * 80 + cc;
            size_t src = (size_t)r * (DIM * 2) + gk + cc;
            CP_ASYNC16(dst,              gAh + src);
            CP_ASYNC16(dst + TBYTES,     gAl + src);
            CP_ASYNC16(dst + 2 * TBYTES, gBh + src);
            CP_ASYNC16(dst + 3 * TBYTES, gBl + src);
        }
    };

    float acc[4][4][4];
#pragma unroll
    for (int i = 0; i < 4; i++)
#pragma unroll
        for (int j = 0; j < 4; j++)
#pragma unroll
            for (int r = 0; r < 4; r++) acc[i][j][r] = 0.0f;

    const int a_r = lane & 15, a_c = (lane >> 4) * 8;
    const int b_r = (lane & 7) + ((lane >> 4) & 1) * 8, b_c = ((lane >> 3) & 1) * 8;

    issue(0, 0);
    CP_COMMIT();

    for (int c = 0; c < NCH; ++c) {
        const int s = c & 1;
        if (c + 1 < NCH) {
            issue(c + 1, s ^ 1);
            CP_COMMIT();
            CP_WAIT(1);
        } else {
            CP_WAIT(0);
        }
        __syncthreads();

        const uint32_t st = sbase + s * STAGEB;
        const uint32_t pAh = st;
        const uint32_t pAl = st + TBYTES;
        const uint32_t pBh = st + 2 * TBYTES;
        const uint32_t pBl = st + 3 * TBYTES;

#pragma unroll
        for (int kk = 0; kk < 32; kk += 16) {
            uint32_t ah[4][4], al[4][4];
#pragma unroll
            for (int mi = 0; mi < 4; mi++) {
                uint32_t off = (uint32_t)((wm + mi * 16 + a_r) * 80 + (kk + a_c) * 2);
                ldsm_x4(ah[mi][0], ah[mi][1], ah[mi][2], ah[mi][3], pAh + off);
                ldsm_x4(al[mi][0], al[mi][1], al[mi][2], al[mi][3], pAl + off);
            }
            uint32_t bh[4][2], bl[4][2];
#pragma unroll
            for (int nb = 0; nb < 2; nb++) {
                uint32_t off = (uint32_t)((wn + nb * 16 + b_r) * 80 + (kk + b_c) * 2);
                uint32_t r0, r1, r2, r3;
                ldsm_x4(r0, r1, r2, r3, pBh + off);
                bh[nb * 2][0] = r0; bh[nb * 2][1] = r1;
                bh[nb * 2 + 1][0] = r2; bh[nb * 2 + 1][1] = r3;
                ldsm_x4(r0, r1, r2, r3, pBl + off);
                bl[nb * 2][0] = r0; bl[nb * 2][1] = r1;
                bl[nb * 2 + 1][0] = r2; bl[nb * 2 + 1][1] = r3;
            }
#pragma unroll
            for (int mi = 0; mi < 4; mi++)
#pragma unroll
                for (int ni = 0; ni < 4; ni++) {
                    mma_bf16(acc[mi][ni][0], acc[mi][ni][1], acc[mi][ni][2], acc[mi][ni][3],
                             ah[mi][0], ah[mi][1], ah[mi][2], ah[mi][3],
                             bh[ni][0], bh[ni][1]);
                    mma_bf16(acc[mi][ni][0], acc[mi][ni][1], acc[mi][ni][2], acc[mi][ni][3],
                             ah[mi][0], ah[mi][1], ah[mi][2], ah[mi][3],
                             bl[ni][0], bl[ni][1]);
                    mma_bf16(acc[mi][ni][0], acc[mi][ni][1], acc[mi][ni][2], acc[mi][ni][3],
                             al[mi][0], al[mi][1], al[mi][2], al[mi][3],
                             bh[ni][0], bh[ni][1]);
                }
        }
        __syncthreads();
    }

    const int er = lane >> 2;
    const int ec = (lane & 3) * 2;
#pragma unroll
    for (int mi = 0; mi < 4; mi++) {
#pragma unroll
        for (int ni = 0; ni < 4; ni++) {
            int col = bn + wn + ni * 8 + ec;
            int row0 = bm + wm + mi * 16 + er;
            int row1 = row0 + 8;
            uint32_t h0, l0, h1, l1;
            split2(acc[mi][ni][0], acc[mi][ni][1], h0, l0);
            split2(acc[mi][ni][2], acc[mi][ni][3], h1, l1);
            *(uint32_t*)(Ch + (size_t)row0 * DIM + col) = h0;
            *(uint32_t*)(Cl + (size_t)row0 * DIM + col) = l0;
            *(uint32_t*)(Ch + (size_t)row1 * DIM + col) = h1;
            *(uint32_t*)(Cl + (size_t)row1 * DIM + col) = l1;
        }
    }
}

__global__ __launch_bounds__(256) void gemm_qk(const __nv_bfloat16* __restrict__ xh,
                                               const __nv_bfloat16* __restrict__ xl,
                                               const __nv_bfloat16* __restrict__ wqh,
                                               const __nv_bfloat16* __restrict__ wql,
                                               const __nv_bfloat16* __restrict__ wkh,
                                               const __nv_bfloat16* __restrict__ wkl,
                                               __nv_bfloat16* __restrict__ qh,
                                               __nv_bfloat16* __restrict__ ql,
                                               __nv_bfloat16* __restrict__ kh,
                                               __nv_bfloat16* __restrict__ kl) {
    extern __shared__ char smem[];
    const __nv_bfloat16* bh = (blockIdx.z == 0) ? wqh : wkh;
    const __nv_bfloat16* bl = (blockIdx.z == 0) ? wql : wkl;
    __nv_bfloat16* oh = (blockIdx.z == 0) ? qh : kh;
    __nv_bfloat16* ol = (blockIdx.z == 0) ? ql : kl;
    gemm3p_body(xh, xl, bh, bl, oh, ol, blockIdx.y * 128, blockIdx.x * 128, smem);
}

// ---------------------------------------------------------------------------
// 2-pass fp16 GEMM: C = A (Bh+Bl)^T. A single fp16; weight rounding cancelled.
// ---------------------------------------------------------------------------
#define H2TILE  10240
#define H2STAGE (3 * H2TILE)
#define H2DYN   (2 * H2STAGE)   // 61440

template <bool BF16OUT>
__device__ __forceinline__ void gemm2p_body(const __half* A, const __half* Bh,
                                            const __half* Bl,
                                            const float* bias, float* C,
                                            __nv_bfloat16* Ch, __nv_bfloat16* Cl,
                                            int bm, int bn, char* smem) {
    const int tid = threadIdx.x;
    const int wid = tid >> 5;
    const int lane = tid & 31;
    const int wm = (wid & 1) * 64;
    const int wn = (wid >> 1) * 32;
    const uint32_t sbase = smem_u32(smem);

    const char* gA  = (const char*)A  + (size_t)bm * (DIM * 2);
    const char* gBh = (const char*)Bh + (size_t)bn * (DIM * 2);
    const char* gBl = (const char*)Bl + (size_t)bn * (DIM * 2);

    auto issue = [&](int c, int s) {
        uint32_t st = sbase + s * H2STAGE;
        const size_t gk = (size_t)c * 64;
#pragma unroll
        for (int rep = 0; rep < 2; rep++) {
            int t = rep ? (tid + 256) : tid;
            int r = t >> 2;
            int cc = (t & 3) << 4;
            uint32_t dst = st + r * 80 + cc;
            size_t src = (size_t)r * (DIM * 2) + gk + cc;
            CP_ASYNC16(dst,              gA + src);
            CP_ASYNC16(dst + H2TILE,     gBh + src);
            CP_ASYNC16(dst + 2 * H2TILE, gBl + src);
        }
    };

    float acc[4][4][4];
#pragma unroll
    for (int i = 0; i < 4; i++)
#pragma unroll
        for (int j = 0; j < 4; j++)
#pragma unroll
            for (int r = 0; r < 4; r++) acc[i][j][r] = 0.0f;

    const int a_r = lane & 15, a_c = (lane >> 4) * 8;
    const int b_r = (lane & 7) + ((lane >> 4) & 1) * 8, b_c = ((lane >> 3) & 1) * 8;

    issue(0, 0);
    CP_COMMIT();

    for (int c = 0; c < NCH; ++c) {
        const int s = c & 1;
        if (c + 1 < NCH) {
            issue(c + 1, s ^ 1);
            CP_COMMIT();
            CP_WAIT(1);
        } else {
            CP_WAIT(0);
        }
        __syncthreads();

        const uint32_t st = sbase + s * H2STAGE;
        const uint32_t pA  = st;
        const uint32_t pBh = st + H2TILE;
        const uint32_t pBl = st + 2 * H2TILE;

#pragma unroll
        for (int kk = 0; kk < 32; kk += 16) {
            uint32_t af[4][4];
#pragma unroll
            for (int mi = 0; mi < 4; mi++) {
                uint32_t off = (uint32_t)((wm + mi * 16 + a_r) * 80 + (kk + a_c) * 2);
                ldsm_x4(af[mi][0], af[mi][1], af[mi][2], af[mi][3], pA + off);
            }
            uint32_t bh[4][2], bl[4][2];
#pragma unroll
            for (int nb = 0; nb < 2; nb++) {
                uint32_t off = (uint32_t)((wn + nb * 16 + b_r) * 80 + (kk + b_c) * 2);
                uint32_t r0, r1, r2, r3;
                ldsm_x4(r0, r1, r2, r3, pBh + off);
                bh[nb * 2][0] = r0; bh[nb * 2][1] = r1;
                bh[nb * 2 + 1][0] = r2; bh[nb * 2 + 1][1] = r3;
                ldsm_x4(r0, r1, r2, r3, pBl + off);
                bl[nb * 2][0] = r0; bl[nb * 2][1] = r1;
                bl[nb * 2 + 1][0] = r2; bl[nb * 2 + 1][1] = r3;
            }
#pragma unroll
            for (int mi = 0; mi < 4; mi++)
#pragma unroll
                for (int ni = 0; ni < 4; ni++) {
                    mma_fp16(acc[mi][ni][0], acc[mi][ni][1], acc[mi][ni][2], acc[mi][ni][3],
                             af[mi][0], af[mi][1], af[mi][2], af[mi][3],
                             bh[ni][0], bh[ni][1]);
                    mma_fp16(acc[mi][ni][0], acc[mi][ni][1], acc[mi][ni][2], acc[mi][ni][3],
                             af[mi][0], af[mi][1], af[mi][2], af[mi][3],
                             bl[ni][0], bl[ni][1]);
                }
        }
        __syncthreads();
    }

    const int er = lane >> 2;
    const int ec = (lane & 3) * 2;
#pragma unroll
    for (int mi = 0; mi < 4; mi++) {
#pragma unroll
        for (int ni = 0; ni < 4; ni++) {
            int col = bn + wn + ni * 8 + ec;
            int row0 = bm + wm + mi * 16 + er;
            int row1 = row0 + 8;
            if (BF16OUT) {
                uint32_t h0, l0, h1, l1;
                split2(acc[mi][ni][0], acc[mi][ni][1], h0, l0);
                split2(acc[mi][ni][2], acc[mi][ni][3], h1, l1);
                *(uint32_t*)(Ch + (size_t)row0 * DIM + col) = h0;
                *(uint32_t*)(Cl + (size_t)row0 * DIM + col) = l0;
                *(uint32_t*)(Ch + (size_t)row1 * DIM + col) = h1;
                *(uint32_t*)(Cl + (size_t)row1 * DIM + col) = l1;
            } else {
                float b0 = bias[col], b1 = bias[col + 1];
                *(float2*)(C + (size_t)row0 * DIM + col) =
                    make_float2(acc[mi][ni][0] + b0, acc[mi][ni][1] + b1);
                *(float2*)(C + (size_t)row1 * DIM + col) =
                    make_float2(acc[mi][ni][2] + b0, acc[mi][ni][3] + b1);
            }
        }
    }
}

__global__ __launch_bounds__(256) void gemm_v(const __half* __restrict__ x16,
                                              const __half* __restrict__ wvh,
                                              const __half* __restrict__ wvl,
                                              __nv_bfloat16* __restrict__ vh,
                                              __nv_bfloat16* __restrict__ vl) {
    extern __shared__ char smem[];
    gemm2p_body<true>(x16, wvh, wvl, nullptr, nullptr, vh, vl,
                      blockIdx.y * 128, blockIdx.x * 128, smem);
}

__global__ __launch_bounds__(256) void gemm_o(const __half* __restrict__ cx,
                                              const __half* __restrict__ woh,
                                              const __half* __restrict__ wol,
                                              const float* __restrict__ bias,
                                              float* __restrict__ C) {
    extern __shared__ char smem[];
    gemm2p_body<false>(cx, woh, wol, bias, C, nullptr, nullptr,
                       blockIdx.y * 128, blockIdx.x * 128, smem);
}

// ---------------------------------------------------------------------------
// HMMA windowed flash attention (verified R8/R9 structure), bf16 hi/lo in,
// fp16 ctx out. 128 threads, 64 queries, pitch 144B, 8-tile arena, 3 CTAs/SM.
// ---------------------------------------------------------------------------
#define APITCH 144
#define ATB    (64 * APITCH)
#define ADYN   (8 * ATB)

__global__ __launch_bounds__(128, 3) void attn_mma(const __nv_bfloat16* __restrict__ Qh,
                                                   const __nv_bfloat16* __restrict__ Ql,
                                                   const __nv_bfloat16* __restrict__ Kh,
                                                   const __nv_bfloat16* __restrict__ Kl,
                                                   const __nv_bfloat16* __restrict__ Vh,
                                                   const __nv_bfloat16* __restrict__ Vl,
                                                   __half* __restrict__ cx) {
    extern __shared__ char smem[];
    const uint32_t s0 = smem_u32(smem);

    const int qb = blockIdx.x * 64;
    const int h = blockIdx.y;
    const int b = blockIdx.z;
    const int tid = threadIdx.x;
    const int warp = tid >> 5;
    const int lane = tid & 31;

    {
        const char* gQh = (const char*)Qh + (((size_t)b * SEQ + qb) * DIM + h * HDIM) * 2;
        const char* gQl = (const char*)Ql + (((size_t)b * SEQ + qb) * DIM + h * HDIM) * 2;
        for (int i = tid; i < 512; i += 128) {
            int r = i >> 3;
            int c = (i & 7) << 4;
            uint32_t dst = s0 + r * APITCH + c;
            size_t src = (size_t)r * (DIM * 2) + c;
            CP_ASYNC16(dst, gQh + src);
            CP_ASYNC16(dst + ATB, gQl + src);
        }
        CP_COMMIT();
        CP_WAIT(0);
        __syncthreads();
    }

    const int a_r = lane & 15, a_c = (lane >> 4) * 8;
    const int b_r = (lane & 7) + ((lane >> 4) & 1) * 8, b_c = ((lane >> 3) & 1) * 8;
    const int v_r = (lane & 7) + ((lane >> 3) & 1) * 8, v_c = ((lane >> 4) & 1) * 8;

    uint32_t qfh[4][4], qfl[4][4];
#pragma unroll
    for (int t = 0; t < 4; t++) {
        uint32_t off = (uint32_t)((warp * 16 + a_r) * APITCH + (t * 16 + a_c) * 2);
        ldsm_x4(qfh[t][0], qfh[t][1], qfh[t][2], qfh[t][3], s0 + off);
        ldsm_x4(qfl[t][0], qfl[t][1], qfl[t][2], qfl[t][3], s0 + ATB + off);
    }
    __syncthreads();

    int kstart = qb - (WIN - 1);
    if (kstart < 0) kstart = 0;
    kstart &= ~63;
    const int ntiles = (qb + 63 - kstart) / 64 + 1;

    auto issueKV = [&](int kt, int s) {
        const size_t base = (((size_t)b * SEQ + kt) * DIM + h * HDIM) * 2;
        const char* pKh = (const char*)Kh + base;
        const char* pKl = (const char*)Kl + base;
        const char* pVh = (const char*)Vh + base;
        const char* pVl = (const char*)Vl + base;
        uint32_t sb = s0 + s * 4 * ATB;
        for (int i = tid; i < 512; i += 128) {
            int r = i >> 3;
            int c = (i & 7) << 4;
            uint32_t dst = sb + r * APITCH + c;
            size_t src = (size_t)r * (DIM * 2) + c;
            CP_ASYNC16(dst,           pKh + src);
            CP_ASYNC16(dst + ATB,     pKl + src);
            CP_ASYNC16(dst + 2 * ATB, pVh + src);
            CP_ASYNC16(dst + 3 * ATB, pVl + src);
        }
    };

    issueKV(kstart, 0);
    CP_COMMIT();
    if (ntiles > 1) {
        issueKV(kstart + 64, 1);
        CP_COMMIT();
    }

    float m0 = -1e30f, m1 = -1e30f, l0 = 0.0f, l1 = 0.0f;
    float o[8][4];
#pragma unroll
    for (int j = 0; j < 8; j++)
#pragma unroll
        for (int r = 0; r < 4; r++) o[j][r] = 0.0f;

    const int row0 = qb + warp * 16 + (lane >> 2);
    const int row1 = row0 + 8;

    for (int it = 0; it < ntiles; ++it) {
        const int kt = kstart + it * 64;
        const int s = it & 1;
        if (it + 1 < ntiles) { CP_WAIT(1); } else { CP_WAIT(0); }
        __syncthreads();

        const uint32_t sKh = s0 + s * 4 * ATB;
        const uint32_t sKl = sKh + ATB;
        const uint32_t sVh = sKh + 2 * ATB;
        const uint32_t sVl = sKh + 3 * ATB;

        float acc[8][4];
#pragma unroll
        for (int j = 0; j < 8; j++)
#pragma unroll
            for (int r = 0; r < 4; r++) acc[j][r] = 0.0f;

#pragma unroll
        for (int t = 0; t < 4; t++) {
#pragma unroll
            for (int g = 0; g < 4; g++) {
                uint32_t off = (uint32_t)((g * 16 + b_r) * APITCH + (t * 16 + b_c) * 2);
                uint32_t kh0, kh1, kh2, kh3, kl0, kl1, kl2, kl3;
                ldsm_x4(kh0, kh1, kh2, kh3, sKh + off);
                ldsm_x4(kl0, kl1, kl2, kl3, sKl + off);
                int n0 = 2 * g, n1 = 2 * g + 1;
                mma_bf16(acc[n0][0], acc[n0][1], acc[n0][2], acc[n0][3],
                         qfh[t][0], qfh[t][1], qfh[t][2], qfh[t][3], kh0, kh1);
                mma_bf16(acc[n1][0], acc[n1][1], acc[n1][2], acc[n1][3],
                         qfh[t][0], qfh[t][1], qfh[t][2], qfh[t][3], kh2, kh3);
                mma_bf16(acc[n0][0], acc[n0][1], acc[n0][2], acc[n0][3],
                         qfh[t][0], qfh[t][1], qfh[t][2], qfh[t][3], kl0, kl1);
                mma_bf16(acc[n1][0], acc[n1][1], acc[n1][2], acc[n1][3],
                         qfh[t][0], qfh[t][1], qfh[t][2], qfh[t][3], kl2, kl3);
                mma_bf16(acc[n0][0], acc[n0][1], acc[n0][2], acc[n0][3],
                         qfl[t][0], qfl[t][1], qfl[t][2], qfl[t][3], kh0, kh1);
                mma_bf16(acc[n1][0], acc[n1][1], acc[n1][2], acc[n1][3],
                         qfl[t][0], qfl[t][1], qfl[t][2], qfl[t][3], kh2, kh3);
            }
        }

        float tmax0 = -1e30f, tmax1 = -1e30f;
#pragma unroll
        for (int j = 0; j < 8; j++) {
            int colb = kt + 8 * j + 2 * (lane & 3);
#pragma unroll
            for (int e = 0; e < 2; e++) {
                int col = colb + e;
                bool v0 = (col <= row0) && (row0 - col < WIN);
                bool v1 = (col <= row1) && (row1 - col < WIN);
                if (!v0) acc[j][e] = -1e30f;
                if (!v1) acc[j][2 + e] = -1e30f;
            }
            tmax0 = fmaxf(tmax0, fmaxf(acc[j][0], acc[j][1]));
            tmax1 = fmaxf(tmax1, fmaxf(acc[j][2], acc[j][3]));
        }
#pragma unroll
        for (int off = 1; off <= 2; off <<= 1) {
            tmax0 = fmaxf(tmax0, __shfl_xor_sync(0xffffffffu, tmax0, off));
            tmax1 = fmaxf(tmax1, __shfl_xor_sync(0xffffffffu, tmax1, off));
        }
        float mn0 = fmaxf(m0, tmax0);
        float mn1 = fmaxf(m1, tmax1);

        float rs0 = 0.0f, rs1 = 0.0f;
#pragma unroll
        for (int j = 0; j < 8; j++) {
            acc[j][0] = __expf(acc[j][0] - mn0);
            acc[j][1] = __expf(acc[j][1] - mn0);
            acc[j][2] = __expf(acc[j][2] - mn1);
            acc[j][3] = __expf(acc[j][3] - mn1);
            rs0 += acc[j][0] + acc[j][1];
            rs1 += acc[j][2] + acc[j][3];
        }
#pragma unroll
        for (int off = 1; off <= 2; off <<= 1) {
            rs0 += __shfl_xor_sync(0xffffffffu, rs0, off);
            rs1 += __shfl_xor_sync(0xffffffffu, rs1, off);
        }
        float corr0 = __expf(m0 - mn0);
        float corr1 = __expf(m1 - mn1);
        l0 = l0 * corr0 + rs0;
        l1 = l1 * corr1 + rs1;
        m0 = mn0;
        m1 = mn1;
#pragma unroll
        for (int j = 0; j < 8; j++) {
            o[j][0] *= corr0;
            o[j][1] *= corr0;
            o[j][2] *= corr1;
            o[j][3] *= corr1;
        }

#pragma unroll
        for (int t = 0; t < 4; t++) {
            uint32_t ph[4], pl[4];
            split2(acc[2 * t][0], acc[2 * t][1], ph[0], pl[0]);
            split2(acc[2 * t][2], acc[2 * t][3], ph[1], pl[1]);
            split2(acc[2 * t + 1][0], acc[2 * t + 1][1], ph[2], pl[2]);
            split2(acc[2 * t + 1][2], acc[2 * t + 1][3], ph[3], pl[3]);
#pragma unroll
            for (int g = 0; g < 4; g++) {
                uint32_t off = (uint32_t)((t * 16 + v_r) * APITCH + (g * 16 + v_c) * 2);
                uint32_t vh0, vh1, vh2, vh3, vl0, vl1, vl2, vl3;
                ldsm_x4_t(vh0, vh1, vh2, vh3, sVh + off);
                ldsm_x4_t(vl0, vl1, vl2, vl3, sVl + off);
                int n0 = 2 * g, n1 = 2 * g + 1;
                mma_bf16(o[n0][0], o[n0][1], o[n0][2], o[n0][3],
                         ph[0], ph[1], ph[2], ph[3], vh0, vh1);
                mma_bf16(o[n1][0], o[n1][1], o[n1][2], o[n1][3],
                         ph[0], ph[1], ph[2], ph[3], vh2, vh3);
                mma_bf16(o[n0][0], o[n0][1], o[n0][2], o[n0][3],
                         ph[0], ph[1], ph[2], ph[3], vl0, vl1);
                mma_bf16(o[n1][0], o[n1][1], o[n1][2], o[n1][3],
                         ph[0], ph[1], ph[2], ph[3], vl2, vl3);
                mma_bf16(o[n0][0], o[n0][1], o[n0][2], o[n0][3],
                         pl[0], pl[1], pl[2], pl[3], vh0, vh1);
                mma_bf16(o[n1][0], o[n1][1], o[n1][2], o[n1][3],
                         pl[0], pl[1], pl[2], pl[3], vh2, vh3);
            }
        }
        __syncthreads();
        if (it + 2 < ntiles) {
            issueKV(kstart + (it + 2) * 64, s);
            CP_COMMIT();
        }
    }

    float inv0 = 1.0f / l0;
    float inv1 = 1.0f / l1;
    const size_t tok0 = (size_t)b * SEQ + row0;
    const size_t tok1 = (size_t)b * SEQ + row1;
    const int colbase = h * HDIM + 2 * (lane & 3);
#pragma unroll
    for (int j = 0; j < 8; j++) {
        int col = colbase + 8 * j;
        *(uint32_t*)(cx + tok0 * DIM + col) = pack_h2(o[j][0] * inv0, o[j][1] * inv0);
        *(uint32_t*)(cx + tok1 * DIM + col) = pack_h2(o[j][2] * inv1, o[j][3] * inv1);
    }
}

// ---------------------------------------------------------------------------
extern "C" void kernel_launch(void* const* d_in, const int* in_sizes, int n_in,
                              void* d_out, int out_size) {
    (void)in_sizes; (void)n_in; (void)out_size;
    const float* X  = (const float*)d_in[0];
    const float* Wq = (const float*)d_in[1];
    const float* Wk = (const float*)d_in[2];
    const float* Wv = (const float*)d_in[3];
    const float* Wo = (const float*)d_in[4];
    const float* bo = (const float*)d_in[5];
    float* out = (float*)d_out;

    __nv_bfloat16 *qh, *ql, *kh, *kl, *vh, *vl, *xh, *xl;
    __nv_bfloat16 *wqh, *wql, *wkh, *wkl;
    __half *x16, *cx16, *wvh16, *wvl16, *woh16, *wol16;
    cudaGetSymbolAddress((void**)&qh, g_qh);
    cudaGetSymbolAddress((void**)&ql, g_ql);
    cudaGetSymbolAddress((void**)&kh, g_kh);
    cudaGetSymbolAddress((void**)&kl, g_kl);
    cudaGetSymbolAddress((void**)&vh, g_vh);
    cudaGetSymbolAddress((void**)&vl, g_vl);
    cudaGetSymbolAddress((void**)&xh, g_xh);
    cudaGetSymbolAddress((void**)&xl, g_xl);
    cudaGetSymbolAddress((void**)&x16, g_x16);
    cudaGetSymbolAddress((void**)&cx16, g_cx16);
    cudaGetSymbolAddress((void**)&wqh, g_wqh);
    cudaGetSymbolAddress((void**)&wql, g_wql);
    cudaGetSymbolAddress((void**)&wkh, g_wkh);
    cudaGetSymbolAddress((void**)&wkl, g_wkl);
    cudaGetSymbolAddress((void**)&wvh16, g_wvh16);
    cudaGetSymbolAddress((void**)&wvl16, g_wvl16);
    cudaGetSymbolAddress((void**)&woh16, g_woh16);
    cudaGetSymbolAddress((void**)&wol16, g_wol16);

    const int DYN3 = 2 * STAGEB;
    cudaFuncSetAttribute(gemm_qk, cudaFuncAttributeMaxDynamicSharedMemorySize, DYN3);
    cudaFuncSetAttribute(gemm_v,  cudaFuncAttributeMaxDynamicSharedMemorySize, H2DYN);
    cudaFuncSetAttribute(gemm_o,  cudaFuncAttributeMaxDynamicSharedMemorySize, H2DYN);
    cudaFuncSetAttribute(attn_mma, cudaFuncAttributeMaxDynamicSharedMemorySize, ADYN);

    const int nX = MROWS * DIM;
    const int nW = DIM * DIM;

    split_x<<<nX / 1024, 256>>>(X, xh, xl, x16);
    dim3 wgrid(nW / 1024, 4);
    conv_w4<<<wgrid, 256>>>(Wq, Wk, Wv, Wo,
                            wqh, wql, wkh, wkl, wvh16, wvl16, woh16, wol16);

    dim3 qk_grid(DIM / 128, MROWS / 128, 2);
    gemm_qk<<<qk_grid, 256, DYN3>>>(xh, xl, wqh, wql, wkh, wkl, qh, ql, kh, kl);

    dim3 vgrid(DIM / 128, MROWS / 128);
    gemm_v<<<vgrid, 256, H2DYN>>>(x16, wvh16, wvl16, vh, vl);

    dim3 attn_grid(SEQ / 64, NHEAD, BATCH);
    attn_mma<<<attn_grid, 128, ADYN>>>(qh, ql, kh, kl, vh, vl, cx16);

    gemm_o<<<vgrid, 256, H2DYN>>>(cx16, woh16, wol16, bo, out);
}

// round 11
// speedup vs baseline: 1.1756x; 1.0003x over previous
#include <cuda_runtime.h>
#include <cuda_bf16.h>
#include <cuda_fp16.h>
#include <stdint.h>

// Problem constants
#define BATCH 4
#define SEQ   2048
#define DIM   1024
#define NHEAD 16
#define HDIM  64
#define WIN   256
#define MROWS (BATCH * SEQ)   // 8192

// ---------------------------------------------------------------------------
// Scratch (device globals: allocation-free rule)
// ---------------------------------------------------------------------------
__device__ __nv_bfloat16 g_qh[MROWS * DIM];
__device__ __nv_bfloat16 g_ql[MROWS * DIM];
__device__ __nv_bfloat16 g_kh[MROWS * DIM];
__device__ __nv_bfloat16 g_kl[MROWS * DIM];
__device__ __nv_bfloat16 g_vh[MROWS * DIM];
__device__ __nv_bfloat16 g_vl[MROWS * DIM];
__device__ __nv_bfloat16 g_xh[MROWS * DIM];
__device__ __nv_bfloat16 g_xl[MROWS * DIM];
__device__ __half g_x16[MROWS * DIM];
__device__ __half g_cx16[MROWS * DIM];
__device__ __nv_bfloat16 g_wqh[DIM * DIM];
__device__ __nv_bfloat16 g_wql[DIM * DIM];
__device__ __nv_bfloat16 g_wkh[DIM * DIM];
__device__ __nv_bfloat16 g_wkl[DIM * DIM];
__device__ __half g_wvh16[DIM * DIM];
__device__ __half g_wvl16[DIM * DIM];
__device__ __half g_woh16[DIM * DIM];
__device__ __half g_wol16[DIM * DIM];

// ---------------------------------------------------------------------------
// Portable PTX helpers
// ---------------------------------------------------------------------------
__device__ __forceinline__ uint32_t smem_u32(const void* p) {
    uint32_t a;
    asm("{ .reg .u64 t; cvta.to.shared.u64 t, %1; cvt.u32.u64 %0, t; }"
        : "=r"(a) : "l"(p));
    return a;
}

#define CP_ASYNC16(dst, src) \
    asm volatile("cp.async.cg.shared.global [%0], [%1], 16;" :: "r"(dst), "l"(src))
#define CP_COMMIT() asm volatile("cp.async.commit_group;" ::: "memory")
#define CP_WAIT(n)  asm volatile("cp.async.wait_group %0;" :: "n"(n) : "memory")

__device__ __forceinline__ void ldsm_x4(uint32_t& r0, uint32_t& r1,
                                        uint32_t& r2, uint32_t& r3, uint32_t addr) {
    asm volatile("ldmatrix.sync.aligned.m8n8.x4.shared.b16 {%0,%1,%2,%3}, [%4];"
                 : "=r"(r0), "=r"(r1), "=r"(r2), "=r"(r3) : "r"(addr));
}

__device__ __forceinline__ void ldsm_x4_t(uint32_t& r0, uint32_t& r1,
                                          uint32_t& r2, uint32_t& r3, uint32_t addr) {
    asm volatile("ldmatrix.sync.aligned.m8n8.x4.trans.shared.b16 {%0,%1,%2,%3}, [%4];"
                 : "=r"(r0), "=r"(r1), "=r"(r2), "=r"(r3) : "r"(addr));
}

__device__ __forceinline__ void mma_bf16(float& c0, float& c1, float& c2, float& c3,
                                         uint32_t a0, uint32_t a1, uint32_t a2, uint32_t a3,
                                         uint32_t b0, uint32_t b1) {
    asm volatile(
        "mma.sync.aligned.m16n8k16.row.col.f32.bf16.bf16.f32 "
        "{%0,%1,%2,%3}, {%4,%5,%6,%7}, {%8,%9}, {%0,%1,%2,%3};"
        : "+f"(c0), "+f"(c1), "+f"(c2), "+f"(c3)
        : "r"(a0), "r"(a1), "r"(a2), "r"(a3), "r"(b0), "r"(b1));
}

__device__ __forceinline__ void mma_fp16(float& c0, float& c1, float& c2, float& c3,
                                         uint32_t a0, uint32_t a1, uint32_t a2, uint32_t a3,
                                         uint32_t b0, uint32_t b1) {
    asm volatile(
        "mma.sync.aligned.m16n8k16.row.col.f32.f16.f16.f32 "
        "{%0,%1,%2,%3}, {%4,%5,%6,%7}, {%8,%9}, {%0,%1,%2,%3};"
        : "+f"(c0), "+f"(c1), "+f"(c2), "+f"(c3)
        : "r"(a0), "r"(a1), "r"(a2), "r"(a3), "r"(b0), "r"(b1));
}

__device__ __forceinline__ uint32_t pack_bf2(__nv_bfloat16 a, __nv_bfloat16 b) {
    __nv_bfloat162 t(a, b);
    return *(uint32_t*)&t;
}

__device__ __forceinline__ void split2(float a, float b, uint32_t& hi, uint32_t& lo) {
    __nv_bfloat16 ha = __float2bfloat16(a), hb = __float2bfloat16(b);
    float ra = a - __bfloat162float(ha);
    float rb = b - __bfloat162float(hb);
    hi = pack_bf2(ha, hb);
    lo = pack_bf2(__float2bfloat16(ra), __float2bfloat16(rb));
}

__device__ __forceinline__ uint32_t pack_h2(float a, float b) {
    __half2 t = __floats2half2_rn(a, b);
    return *(uint32_t*)&t;
}

// fp16 hi/lo split of two floats
__device__ __forceinline__ void split2h(float a, float b, uint32_t& hi, uint32_t& lo) {
    __half ha = __float2half_rn(a), hb = __float2half_rn(b);
    float ra = a - __half2float(ha);
    float rb = b - __half2float(hb);
    __half2 th(ha, hb);
    __half2 tl(__float2half_rn(ra), __float2half_rn(rb));
    hi = *(uint32_t*)&th;
    lo = *(uint32_t*)&tl;
}

// ---------------------------------------------------------------------------
// converts
// ---------------------------------------------------------------------------
// X -> bf16 hi/lo (for Q/K proj) AND single fp16 (for V proj)
__global__ __launch_bounds__(256) void split_x(const float* __restrict__ src,
                                               __nv_bfloat16* __restrict__ hi,
                                               __nv_bfloat16* __restrict__ lo,
                                               __half* __restrict__ h16) {
    int i = (blockIdx.x * 256 + threadIdx.x) * 4;
    float4 x = *(const float4*)(src + i);
    uint32_t h0, l0, h1, l1;
    split2(x.x, x.y, h0, l0);
    split2(x.z, x.w, h1, l1);
    uint32_t* ph = (uint32_t*)(hi + i);
    uint32_t* pl = (uint32_t*)(lo + i);
    uint32_t* p16 = (uint32_t*)(h16 + i);
    ph[0] = h0; ph[1] = h1;
    pl[0] = l0; pl[1] = l1;
    p16[0] = pack_h2(x.x, x.y);
    p16[1] = pack_h2(x.z, x.w);
}

// weights: Wq,Wk -> bf16 hi/lo; Wv,Wo -> fp16 hi/lo
__global__ __launch_bounds__(256) void conv_w4(const float* __restrict__ s0,
                                               const float* __restrict__ s1,
                                               const float* __restrict__ s2,
                                               const float* __restrict__ s3,
                                               __nv_bfloat16* __restrict__ bq_h,
                                               __nv_bfloat16* __restrict__ bq_l,
                                               __nv_bfloat16* __restrict__ bk_h,
                                               __nv_bfloat16* __restrict__ bk_l,
                                               __half* __restrict__ hv_h,
                                               __half* __restrict__ hv_l,
                                               __half* __restrict__ ho_h,
                                               __half* __restrict__ ho_l) {
    int w = blockIdx.y;
    int i = (blockIdx.x * 256 + threadIdx.x) * 4;
    if (w < 2) {
        const float* src = (w == 0) ? s0 : s1;
        __nv_bfloat16* hi = (w == 0) ? bq_h : bk_h;
        __nv_bfloat16* lo = (w == 0) ? bq_l : bk_l;
        float4 x = *(const float4*)(src + i);
        uint32_t h0, l0, h1, l1;
        split2(x.x, x.y, h0, l0);
        split2(x.z, x.w, h1, l1);
        uint32_t* ph = (uint32_t*)(hi + i);
        uint32_t* pl = (uint32_t*)(lo + i);
        ph[0] = h0; ph[1] = h1;
        pl[0] = l0; pl[1] = l1;
    } else {
        const float* src = (w == 2) ? s2 : s3;
        __half* hi = (w == 2) ? hv_h : ho_h;
        __half* lo = (w == 2) ? hv_l : ho_l;
        float4 x = *(const float4*)(src + i);
        uint32_t h0, l0, h1, l1;
        split2h(x.x, x.y, h0, l0);
        split2h(x.z, x.w, h1, l1);
        uint32_t* ph = (uint32_t*)(hi + i);
        uint32_t* pl = (uint32_t*)(lo + i);
        ph[0] = h0; ph[1] = h1;
        pl[0] = l0; pl[1] = l1;
    }
}

// ---------------------------------------------------------------------------
// 3-pass bf16 GEMM (verified R3-R8): C = (Ah+Al)(Bh+Bl)^T, bf16 hi/lo out
// ---------------------------------------------------------------------------
#define GP      40
#define TBYTES  (128 * GP * 2)
#define STAGEB  (4 * TBYTES)
#define NCH     (DIM / 32)

__device__ __forceinline__ void gemm3p_body(const __nv_bfloat16* Ah, const __nv_bfloat16* Al,
                                            const __nv_bfloat16* Bh, const __nv_bfloat16* Bl,
                                            __nv_bfloat16* Ch, __nv_bfloat16* Cl,
                                            int bm, int bn, char* smem) {
    const int tid = threadIdx.x;
    const int wid = tid >> 5;
    const int lane = tid & 31;
    const int wm = (wid & 1) * 64;
    const int wn = (wid >> 1) * 32;
    const uint32_t sbase = smem_u32(smem);

    const char* gAh = (const char*)Ah + (size_t)bm * (DIM * 2);
    const char* gAl = (const char*)Al + (size_t)bm * (DIM * 2);
    const char* gBh = (const char*)Bh + (size_t)bn * (DIM * 2);
    const char* gBl = (const char*)Bl + (size_t)bn * (DIM * 2);

    auto issue = [&](int c, int s) {
        uint32_t st = sbase + s * STAGEB;
        const size_t gk = (size_t)c * 64;
#pragma unroll
        for (int rep = 0; rep < 2; rep++) {
            int t = rep ? (tid + 256) : tid;
            int r = t >> 2;
            int cc = (t & 3) << 4;
            uint32_t dst = st + r * 80 + cc;
            size_t src = (size_t)r * (DIM * 2) + gk + cc;
            CP_ASYNC16(dst,              gAh + src);
            CP_ASYNC16(dst + TBYTES,     gAl + src);
            CP_ASYNC16(dst + 2 * TBYTES, gBh + src);
            CP_ASYNC16(dst + 3 * TBYTES, gBl + src);
        }
    };

    float acc[4][4][4];
#pragma unroll
    for (int i = 0; i < 4; i++)
#pragma unroll
        for (int j = 0; j < 4; j++)
#pragma unroll
            for (int r = 0; r < 4; r++) acc[i][j][r] = 0.0f;

    const int a_r = lane & 15, a_c = (lane >> 4) * 8;
    const int b_r = (lane & 7) + ((lane >> 4) & 1) * 8, b_c = ((lane >> 3) & 1) * 8;

    issue(0, 0);
    CP_COMMIT();

    for (int c = 0; c < NCH; ++c) {
        const int s = c & 1;
        if (c + 1 < NCH) {
            issue(c + 1, s ^ 1);
            CP_COMMIT();
            CP_WAIT(1);
        } else {
            CP_WAIT(0);
        }
        __syncthreads();

        const uint32_t st = sbase + s * STAGEB;
        const uint32_t pAh = st;
        const uint32_t pAl = st + TBYTES;
        const uint32_t pBh = st + 2 * TBYTES;
        const uint32_t pBl = st + 3 * TBYTES;

#pragma unroll
        for (int kk = 0; kk < 32; kk += 16) {
            uint32_t ah[4][4], al[4][4];
#pragma unroll
            for (int mi = 0; mi < 4; mi++) {
                uint32_t off = (uint32_t)((wm + mi * 16 + a_r) * 80 + (kk + a_c) * 2);
                ldsm_x4(ah[mi][0], ah[mi][1], ah[mi][2], ah[mi][3], pAh + off);
                ldsm_x4(al[mi][0], al[mi][1], al[mi][2], al[mi][3], pAl + off);
            }
            uint32_t bh[4][2], bl[4][2];
#pragma unroll
            for (int nb = 0; nb < 2; nb++) {
                uint32_t off = (uint32_t)((wn + nb * 16 + b_r) * 80 + (kk + b_c) * 2);
                uint32_t r0, r1, r2, r3;
                ldsm_x4(r0, r1, r2, r3, pBh + off);
                bh[nb * 2][0] = r0; bh[nb * 2][1] = r1;
                bh[nb * 2 + 1][0] = r2; bh[nb * 2 + 1][1] = r3;
                ldsm_x4(r0, r1, r2, r3, pBl + off);
                bl[nb * 2][0] = r0; bl[nb * 2][1] = r1;
                bl[nb * 2 + 1][0] = r2; bl[nb * 2 + 1][1] = r3;
            }
#pragma unroll
            for (int mi = 0; mi < 4; mi++)
#pragma unroll
                for (int ni = 0; ni < 4; ni++) {
                    mma_bf16(acc[mi][ni][0], acc[mi][ni][1], acc[mi][ni][2], acc[mi][ni][3],
                             ah[mi][0], ah[mi][1], ah[mi][2], ah[mi][3],
                             bh[ni][0], bh[ni][1]);
                    mma_bf16(acc[mi][ni][0], acc[mi][ni][1], acc[mi][ni][2], acc[mi][ni][3],
                             ah[mi][0], ah[mi][1], ah[mi][2], ah[mi][3],
                             bl[ni][0], bl[ni][1]);
                    mma_bf16(acc[mi][ni][0], acc[mi][ni][1], acc[mi][ni][2], acc[mi][ni][3],
                             al[mi][0], al[mi][1], al[mi][2], al[mi][3],
                             bh[ni][0], bh[ni][1]);
                }
        }
        __syncthreads();
    }

    const int er = lane >> 2;
    const int ec = (lane & 3) * 2;
#pragma unroll
    for (int mi = 0; mi < 4; mi++) {
#pragma unroll
        for (int ni = 0; ni < 4; ni++) {
            int col = bn + wn + ni * 8 + ec;
            int row0 = bm + wm + mi * 16 + er;
            int row1 = row0 + 8;
            uint32_t h0, l0, h1, l1;
            split2(acc[mi][ni][0], acc[mi][ni][1], h0, l0);
            split2(acc[mi][ni][2], acc[mi][ni][3], h1, l1);
            *(uint32_t*)(Ch + (size_t)row0 * DIM + col) = h0;
            *(uint32_t*)(Cl + (size_t)row0 * DIM + col) = l0;
            *(uint32_t*)(Ch + (size_t)row1 * DIM + col) = h1;
            *(uint32_t*)(Cl + (size_t)row1 * DIM + col) = l1;
        }
    }
}

__global__ __launch_bounds__(256) void gemm_qk(const __nv_bfloat16* __restrict__ xh,
                                               const __nv_bfloat16* __restrict__ xl,
                                               const __nv_bfloat16* __restrict__ wqh,
                                               const __nv_bfloat16* __restrict__ wql,
                                               const __nv_bfloat16* __restrict__ wkh,
                                               const __nv_bfloat16* __restrict__ wkl,
                                               __nv_bfloat16* __restrict__ qh,
                                               __nv_bfloat16* __restrict__ ql,
                                               __nv_bfloat16* __restrict__ kh,
                                               __nv_bfloat16* __restrict__ kl) {
    extern __shared__ char smem[];
    const __nv_bfloat16* bh = (blockIdx.z == 0) ? wqh : wkh;
    const __nv_bfloat16* bl = (blockIdx.z == 0) ? wql : wkl;
    __nv_bfloat16* oh = (blockIdx.z == 0) ? qh : kh;
    __nv_bfloat16* ol = (blockIdx.z == 0) ? ql : kl;
    gemm3p_body(xh, xl, bh, bl, oh, ol, blockIdx.y * 128, blockIdx.x * 128, smem);
}

// ---------------------------------------------------------------------------
// 2-pass fp16 GEMM: C = A (Bh+Bl)^T. A single fp16; weight rounding cancelled.
// ---------------------------------------------------------------------------
#define H2TILE  10240
#define H2STAGE (3 * H2TILE)
#define H2DYN   (2 * H2STAGE)   // 61440

template <bool BF16OUT>
__device__ __forceinline__ void gemm2p_body(const __half* A, const __half* Bh,
                                            const __half* Bl,
                                            const float* bias, float* C,
                                            __nv_bfloat16* Ch, __nv_bfloat16* Cl,
                                            int bm, int bn, char* smem) {
    const int tid = threadIdx.x;
    const int wid = tid >> 5;
    const int lane = tid & 31;
    const int wm = (wid & 1) * 64;
    const int wn = (wid >> 1) * 32;
    const uint32_t sbase = smem_u32(smem);

    const char* gA  = (const char*)A  + (size_t)bm * (DIM * 2);
    const char* gBh = (const char*)Bh + (size_t)bn * (DIM * 2);
    const char* gBl = (const char*)Bl + (size_t)bn * (DIM * 2);

    auto issue = [&](int c, int s) {
        uint32_t st = sbase + s * H2STAGE;
        const size_t gk = (size_t)c * 64;
#pragma unroll
        for (int rep = 0; rep < 2; rep++) {
            int t = rep ? (tid + 256) : tid;
            int r = t >> 2;
            int cc = (t & 3) << 4;
            uint32_t dst = st + r * 80 + cc;
            size_t src = (size_t)r * (DIM * 2) + gk + cc;
            CP_ASYNC16(dst,              gA + src);
            CP_ASYNC16(dst + H2TILE,     gBh + src);
            CP_ASYNC16(dst + 2 * H2TILE, gBl + src);
        }
    };

    float acc[4][4][4];
#pragma unroll
    for (int i = 0; i < 4; i++)
#pragma unroll
        for (int j = 0; j < 4; j++)
#pragma unroll
            for (int r = 0; r < 4; r++) acc[i][j][r] = 0.0f;

    const int a_r = lane & 15, a_c = (lane >> 4) * 8;
    const int b_r = (lane & 7) + ((lane >> 4) & 1) * 8, b_c = ((lane >> 3) & 1) * 8;

    issue(0, 0);
    CP_COMMIT();

    for (int c = 0; c < NCH; ++c) {
        const int s = c & 1;
        if (c + 1 < NCH) {
            issue(c + 1, s ^ 1);
            CP_COMMIT();
            CP_WAIT(1);
        } else {
            CP_WAIT(0);
        }
        __syncthreads();

        const uint32_t st = sbase + s * H2STAGE;
        const uint32_t pA  = st;
        const uint32_t pBh = st + H2TILE;
        const uint32_t pBl = st + 2 * H2TILE;

#pragma unroll
        for (int kk = 0; kk < 32; kk += 16) {
            uint32_t af[4][4];
#pragma unroll
            for (int mi = 0; mi < 4; mi++) {
                uint32_t off = (uint32_t)((wm + mi * 16 + a_r) * 80 + (kk + a_c) * 2);
                ldsm_x4(af[mi][0], af[mi][1], af[mi][2], af[mi][3], pA + off);
            }
            uint32_t bh[4][2], bl[4][2];
#pragma unroll
            for (int nb = 0; nb < 2; nb++) {
                uint32_t off = (uint32_t)((wn + nb * 16 + b_r) * 80 + (kk + b_c) * 2);
                uint32_t r0, r1, r2, r3;
                ldsm_x4(r0, r1, r2, r3, pBh + off);
                bh[nb * 2][0] = r0; bh[nb * 2][1] = r1;
                bh[nb * 2 + 1][0] = r2; bh[nb * 2 + 1][1] = r3;
                ldsm_x4(r0, r1, r2, r3, pBl + off);
                bl[nb * 2][0] = r0; bl[nb * 2][1] = r1;
                bl[nb * 2 + 1][0] = r2; bl[nb * 2 + 1][1] = r3;
            }
#pragma unroll
            for (int mi = 0; mi < 4; mi++)
#pragma unroll
                for (int ni = 0; ni < 4; ni++) {
                    mma_fp16(acc[mi][ni][0], acc[mi][ni][1], acc[mi][ni][2], acc[mi][ni][3],
                             af[mi][0], af[mi][1], af[mi][2], af[mi][3],
                             bh[ni][0], bh[ni][1]);
                    mma_fp16(acc[mi][ni][0], acc[mi][ni][1], acc[mi][ni][2], acc[mi][ni][3],
                             af[mi][0], af[mi][1], af[mi][2], af[mi][3],
                             bl[ni][0], bl[ni][1]);
                }
        }
        __syncthreads();
    }

    const int er = lane >> 2;
    const int ec = (lane & 3) * 2;
#pragma unroll
    for (int mi = 0; mi < 4; mi++) {
#pragma unroll
        for (int ni = 0; ni < 4; ni++) {
            int col = bn + wn + ni * 8 + ec;
            int row0 = bm + wm + mi * 16 + er;
            int row1 = row0 + 8;
            if (BF16OUT) {
                uint32_t h0, l0, h1, l1;
                split2(acc[mi][ni][0], acc[mi][ni][1], h0, l0);
                split2(acc[mi][ni][2], acc[mi][ni][3], h1, l1);
                *(uint32_t*)(Ch + (size_t)row0 * DIM + col) = h0;
                *(uint32_t*)(Cl + (size_t)row0 * DIM + col) = l0;
                *(uint32_t*)(Ch + (size_t)row1 * DIM + col) = h1;
                *(uint32_t*)(Cl + (size_t)row1 * DIM + col) = l1;
            } else {
                float b0 = bias[col], b1 = bias[col + 1];
                *(float2*)(C + (size_t)row0 * DIM + col) =
                    make_float2(acc[mi][ni][0] + b0, acc[mi][ni][1] + b1);
                *(float2*)(C + (size_t)row1 * DIM + col) =
                    make_float2(acc[mi][ni][2] + b0, acc[mi][ni][3] + b1);
            }
        }
    }
}

__global__ __launch_bounds__(256) void gemm_v(const __half* __restrict__ x16,
                                              const __half* __restrict__ wvh,
                                              const __half* __restrict__ wvl,
                                              __nv_bfloat16* __restrict__ vh,
                                              __nv_bfloat16* __restrict__ vl) {
    extern __shared__ char smem[];
    gemm2p_body<true>(x16, wvh, wvl, nullptr, nullptr, vh, vl,
                      blockIdx.y * 128, blockIdx.x * 128, smem);
}

__global__ __launch_bounds__(256) void gemm_o(const __half* __restrict__ cx,
                                              const __half* __restrict__ woh,
                                              const __half* __restrict__ wol,
                                              const float* __restrict__ bias,
                                              float* __restrict__ C) {
    extern __shared__ char smem[];
    gemm2p_body<false>(cx, woh, wol, bias, C, nullptr, nullptr,
                       blockIdx.y * 128, blockIdx.x * 128, smem);
}

// ---------------------------------------------------------------------------
// HMMA windowed flash attention (verified R8/R9 structure), bf16 hi/lo in,
// fp16 ctx out. 128 threads, 64 queries, pitch 144B, 8-tile arena, 3 CTAs/SM.
// ---------------------------------------------------------------------------
#define APITCH 144
#define ATB    (64 * APITCH)
#define ADYN   (8 * ATB)

__global__ __launch_bounds__(128, 3) void attn_mma(const __nv_bfloat16* __restrict__ Qh,
                                                   const __nv_bfloat16* __restrict__ Ql,
                                                   const __nv_bfloat16* __restrict__ Kh,
                                                   const __nv_bfloat16* __restrict__ Kl,
                                                   const __nv_bfloat16* __restrict__ Vh,
                                                   const __nv_bfloat16* __restrict__ Vl,
                                                   __half* __restrict__ cx) {
    extern __shared__ char smem[];
    const uint32_t s0 = smem_u32(smem);

    const int qb = blockIdx.x * 64;
    const int h = blockIdx.y;
    const int b = blockIdx.z;
    const int tid = threadIdx.x;
    const int warp = tid >> 5;
    const int lane = tid & 31;

    {
        const char* gQh = (const char*)Qh + (((size_t)b * SEQ + qb) * DIM + h * HDIM) * 2;
        const char* gQl = (const char*)Ql + (((size_t)b * SEQ + qb) * DIM + h * HDIM) * 2;
        for (int i = tid; i < 512; i += 128) {
            int r = i >> 3;
            int c = (i & 7) << 4;
            uint32_t dst = s0 + r * APITCH + c;
            size_t src = (size_t)r * (DIM * 2) + c;
            CP_ASYNC16(dst, gQh + src);
            CP_ASYNC16(dst + ATB, gQl + src);
        }
        CP_COMMIT();
        CP_WAIT(0);
        __syncthreads();
    }

    const int a_r = lane & 15, a_c = (lane >> 4) * 8;
    const int b_r = (lane & 7) + ((lane >> 4) & 1) * 8, b_c = ((lane >> 3) & 1) * 8;
    const int v_r = (lane & 7) + ((lane >> 3) & 1) * 8, v_c = ((lane >> 4) & 1) * 8;

    uint32_t qfh[4][4], qfl[4][4];
#pragma unroll
    for (int t = 0; t < 4; t++) {
        uint32_t off = (uint32_t)((warp * 16 + a_r) * APITCH + (t * 16 + a_c) * 2);
        ldsm_x4(qfh[t][0], qfh[t][1], qfh[t][2], qfh[t][3], s0 + off);
        ldsm_x4(qfl[t][0], qfl[t][1], qfl[t][2], qfl[t][3], s0 + ATB + off);
    }
    __syncthreads();

    int kstart = qb - (WIN - 1);
    if (kstart < 0) kstart = 0;
    kstart &= ~63;
    const int ntiles = (qb + 63 - kstart) / 64 + 1;

    auto issueKV = [&](int kt, int s) {
        const size_t base = (((size_t)b * SEQ + kt) * DIM + h * HDIM) * 2;
        const char* pKh = (const char*)Kh + base;
        const char* pKl = (const char*)Kl + base;
        const char* pVh = (const char*)Vh + base;
        const char* pVl = (const char*)Vl + base;
        uint32_t sb = s0 + s * 4 * ATB;
        for (int i = tid; i < 512; i += 128) {
            int r = i >> 3;
            int c = (i & 7) << 4;
            uint32_t dst = sb + r * APITCH + c;
            size_t src = (size_t)r * (DIM * 2) + c;
            CP_ASYNC16(dst,           pKh + src);
            CP_ASYNC16(dst + ATB,     pKl + src);
            CP_ASYNC16(dst + 2 * ATB, pVh + src);
            CP_ASYNC16(dst + 3 * ATB, pVl + src);
        }
    };

    issueKV(kstart, 0);
    CP_COMMIT();
    if (ntiles > 1) {
        issueKV(kstart + 64, 1);
        CP_COMMIT();
    }

    float m0 = -1e30f, m1 = -1e30f, l0 = 0.0f, l1 = 0.0f;
    float o[8][4];
#pragma unroll
    for (int j = 0; j < 8; j++)
#pragma unroll
        for (int r = 0; r < 4; r++) o[j][r] = 0.0f;

    const int row0 = qb + warp * 16 + (lane >> 2);
    const int row1 = row0 + 8;

    for (int it = 0; it < ntiles; ++it) {
        const int kt = kstart + it * 64;
        const int s = it & 1;
        if (it + 1 < ntiles) { CP_WAIT(1); } else { CP_WAIT(0); }
        __syncthreads();

        const uint32_t sKh = s0 + s * 4 * ATB;
        const uint32_t sKl = sKh + ATB;
        const uint32_t sVh = sKh + 2 * ATB;
        const uint32_t sVl = sKh + 3 * ATB;

        float acc[8][4];
#pragma unroll
        for (int j = 0; j < 8; j++)
#pragma unroll
            for (int r = 0; r < 4; r++) acc[j][r] = 0.0f;

#pragma unroll
        for (int t = 0; t < 4; t++) {
#pragma unroll
            for (int g = 0; g < 4; g++) {
                uint32_t off = (uint32_t)((g * 16 + b_r) * APITCH + (t * 16 + b_c) * 2);
                uint32_t kh0, kh1, kh2, kh3, kl0, kl1, kl2, kl3;
                ldsm_x4(kh0, kh1, kh2, kh3, sKh + off);
                ldsm_x4(kl0, kl1, kl2, kl3, sKl + off);
                int n0 = 2 * g, n1 = 2 * g + 1;
                mma_bf16(acc[n0][0], acc[n0][1], acc[n0][2], acc[n0][3],
                         qfh[t][0], qfh[t][1], qfh[t][2], qfh[t][3], kh0, kh1);
                mma_bf16(acc[n1][0], acc[n1][1], acc[n1][2], acc[n1][3],
                         qfh[t][0], qfh[t][1], qfh[t][2], qfh[t][3], kh2, kh3);
                mma_bf16(acc[n0][0], acc[n0][1], acc[n0][2], acc[n0][3],
                         qfh[t][0], qfh[t][1], qfh[t][2], qfh[t][3], kl0, kl1);
                mma_bf16(acc[n1][0], acc[n1][1], acc[n1][2], acc[n1][3],
                         qfh[t][0], qfh[t][1], qfh[t][2], qfh[t][3], kl2, kl3);
                mma_bf16(acc[n0][0], acc[n0][1], acc[n0][2], acc[n0][3],
                         qfl[t][0], qfl[t][1], qfl[t][2], qfl[t][3], kh0, kh1);
                mma_bf16(acc[n1][0], acc[n1][1], acc[n1][2], acc[n1][3],
                         qfl[t][0], qfl[t][1], qfl[t][2], qfl[t][3], kh2, kh3);
            }
        }

        float tmax0 = -1e30f, tmax1 = -1e30f;
#pragma unroll
        for (int j = 0; j < 8; j++) {
            int colb = kt + 8 * j + 2 * (lane & 3);
#pragma unroll
            for (int e = 0; e < 2; e++) {
                int col = colb + e;
                bool v0 = (col <= row0) && (row0 - col < WIN);
                bool v1 = (col <= row1) && (row1 - col < WIN);
                if (!v0) acc[j][e] = -1e30f;
                if (!v1) acc[j][2 + e] = -1e30f;
            }
            tmax0 = fmaxf(tmax0, fmaxf(acc[j][0], acc[j][1]));
            tmax1 = fmaxf(tmax1, fmaxf(acc[j][2], acc[j][3]));
        }
#pragma unroll
        for (int off = 1; off <= 2; off <<= 1) {
            tmax0 = fmaxf(tmax0, __shfl_xor_sync(0xffffffffu, tmax0, off));
            tmax1 = fmaxf(tmax1, __shfl_xor_sync(0xffffffffu, tmax1, off));
        }
        float mn0 = fmaxf(m0, tmax0);
        float mn1 = fmaxf(m1, tmax1);

        float rs0 = 0.0f, rs1 = 0.0f;
#pragma unroll
        for (int j = 0; j < 8; j++) {
            acc[j][0] = __expf(acc[j][0] - mn0);
            acc[j][1] = __expf(acc[j][1] - mn0);
            acc[j][2] = __expf(acc[j][2] - mn1);
            acc[j][3] = __expf(acc[j][3] - mn1);
            rs0 += acc[j][0] + acc[j][1];
            rs1 += acc[j][2] + acc[j][3];
        }
#pragma unroll
        for (int off = 1; off <= 2; off <<= 1) {
            rs0 += __shfl_xor_sync(0xffffffffu, rs0, off);
            rs1 += __shfl_xor_sync(0xffffffffu, rs1, off);
        }
        float corr0 = __expf(m0 - mn0);
        float corr1 = __expf(m1 - mn1);
        l0 = l0 * corr0 + rs0;
        l1 = l1 * corr1 + rs1;
        m0 = mn0;
        m1 = mn1;
#pragma unroll
        for (int j = 0; j < 8; j++) {
            o[j][0] *= corr0;
            o[j][1] *= corr0;
            o[j][2] *= corr1;
            o[j][3] *= corr1;
        }

#pragma unroll
        for (int t = 0; t < 4; t++) {
            uint32_t ph[4], pl[4];
            split2(acc[2 * t][0], acc[2 * t][1], ph[0], pl[0]);
            split2(acc[2 * t][2], acc[2 * t][3], ph[1], pl[1]);
            split2(acc[2 * t + 1][0], acc[2 * t + 1][1], ph[2], pl[2]);
            split2(acc[2 * t + 1][2], acc[2 * t + 1][3], ph[3], pl[3]);
#pragma unroll
            for (int g = 0; g < 4; g++) {
                uint32_t off = (uint32_t)((t * 16 + v_r) * APITCH + (g * 16 + v_c) * 2);
                uint32_t vh0, vh1, vh2, vh3, vl0, vl1, vl2, vl3;
                ldsm_x4_t(vh0, vh1, vh2, vh3, sVh + off);
                ldsm_x4_t(vl0, vl1, vl2, vl3, sVl + off);
                int n0 = 2 * g, n1 = 2 * g + 1;
                mma_bf16(o[n0][0], o[n0][1], o[n0][2], o[n0][3],
                         ph[0], ph[1], ph[2], ph[3], vh0, vh1);
                mma_bf16(o[n1][0], o[n1][1], o[n1][2], o[n1][3],
                         ph[0], ph[1], ph[2], ph[3], vh2, vh3);
                mma_bf16(o[n0][0], o[n0][1], o[n0][2], o[n0][3],
                         ph[0], ph[1], ph[2], ph[3], vl0, vl1);
                mma_bf16(o[n1][0], o[n1][1], o[n1][2], o[n1][3],
                         ph[0], ph[1], ph[2], ph[3], vl2, vl3);
                mma_bf16(o[n0][0], o[n0][1], o[n0][2], o[n0][3],
                         pl[0], pl[1], pl[2], pl[3], vh0, vh1);
                mma_bf16(o[n1][0], o[n1][1], o[n1][2], o[n1][3],
                         pl[0], pl[1], pl[2], pl[3], vh2, vh3);
            }
        }
        __syncthreads();
        if (it + 2 < ntiles) {
            issueKV(kstart + (it + 2) * 64, s);
            CP_COMMIT();
        }
    }

    float inv0 = 1.0f / l0;
    float inv1 = 1.0f / l1;
    const size_t tok0 = (size_t)b * SEQ + row0;
    const size_t tok1 = (size_t)b * SEQ + row1;
    const int colbase = h * HDIM + 2 * (lane & 3);
#pragma unroll
    for (int j = 0; j < 8; j++) {
        int col = colbase + 8 * j;
        *(uint32_t*)(cx + tok0 * DIM + col) = pack_h2(o[j][0] * inv0, o[j][1] * inv0);
        *(uint32_t*)(cx + tok1 * DIM + col) = pack_h2(o[j][2] * inv1, o[j][3] * inv1);
    }
}

// ---------------------------------------------------------------------------
extern "C" void kernel_launch(void* const* d_in, const int* in_sizes, int n_in,
                              void* d_out, int out_size) {
    (void)in_sizes; (void)n_in; (void)out_size;
    const float* X  = (const float*)d_in[0];
    const float* Wq = (const float*)d_in[1];
    const float* Wk = (const float*)d_in[2];
    const float* Wv = (const float*)d_in[3];
    const float* Wo = (const float*)d_in[4];
    const float* bo = (const float*)d_in[5];
    float* out = (float*)d_out;

    __nv_bfloat16 *qh, *ql, *kh, *kl, *vh, *vl, *xh, *xl;
    __nv_bfloat16 *wqh, *wql, *wkh, *wkl;
    __half *x16, *cx16, *wvh16, *wvl16, *woh16, *wol16;
    cudaGetSymbolAddress((void**)&qh, g_qh);
    cudaGetSymbolAddress((void**)&ql, g_ql);
    cudaGetSymbolAddress((void**)&kh, g_kh);
    cudaGetSymbolAddress((void**)&kl, g_kl);
    cudaGetSymbolAddress((void**)&vh, g_vh);
    cudaGetSymbolAddress((void**)&vl, g_vl);
    cudaGetSymbolAddress((void**)&xh, g_xh);
    cudaGetSymbolAddress((void**)&xl, g_xl);
    cudaGetSymbolAddress((void**)&x16, g_x16);
    cudaGetSymbolAddress((void**)&cx16, g_cx16);
    cudaGetSymbolAddress((void**)&wqh, g_wqh);
    cudaGetSymbolAddress((void**)&wql, g_wql);
    cudaGetSymbolAddress((void**)&wkh, g_wkh);
    cudaGetSymbolAddress((void**)&wkl, g_wkl);
    cudaGetSymbolAddress((void**)&wvh16, g_wvh16);
    cudaGetSymbolAddress((void**)&wvl16, g_wvl16);
    cudaGetSymbolAddress((void**)&woh16, g_woh16);
    cudaGetSymbolAddress((void**)&wol16, g_wol16);

    const int DYN3 = 2 * STAGEB;
    cudaFuncSetAttribute(gemm_qk, cudaFuncAttributeMaxDynamicSharedMemorySize, DYN3);
    cudaFuncSetAttribute(gemm_v,  cudaFuncAttributeMaxDynamicSharedMemorySize, H2DYN);
    cudaFuncSetAttribute(gemm_o,  cudaFuncAttributeMaxDynamicSharedMemorySize, H2DYN);
    cudaFuncSetAttribute(attn_mma, cudaFuncAttributeMaxDynamicSharedMemorySize, ADYN);

    const int nX = MROWS * DIM;
    const int nW = DIM * DIM;

    split_x<<<nX / 1024, 256>>>(X, xh, xl, x16);
    dim3 wgrid(nW / 1024, 4);
    conv_w4<<<wgrid, 256>>>(Wq, Wk, Wv, Wo,
                            wqh, wql, wkh, wkl, wvh16, wvl16, woh16, wol16);

    dim3 qk_grid(DIM / 128, MROWS / 128, 2);
    gemm_qk<<<qk_grid, 256, DYN3>>>(xh, xl, wqh, wql, wkh, wkl, qh, ql, kh, kl);

    dim3 vgrid(DIM / 128, MROWS / 128);
    gemm_v<<<vgrid, 256, H2DYN>>>(x16, wvh16, wvl16, vh, vl);

    dim3 attn_grid(SEQ / 64, NHEAD, BATCH);
    attn_mma<<<attn_grid, 128, ADYN>>>(qh, ql, kh, kl, vh, vl, cx16);

    gemm_o<<<vgrid, 256, H2DYN>>>(cx16, woh16, wol16, bo, out);
}

// round 12
// speedup vs baseline: 1.1760x; 1.0003x over previous
#include <cuda_runtime.h>
#include <cuda_bf16.h>
#include <cuda_fp16.h>
#include <stdint.h>

// Problem constants
#define BATCH 4
#define SEQ   2048
#define DIM   1024
#define NHEAD 16
#define HDIM  64
#define WIN   256
#define MROWS (BATCH * SEQ)   // 8192

// ---------------------------------------------------------------------------
// Scratch (device globals: allocation-free rule)
// ---------------------------------------------------------------------------
__device__ __nv_bfloat16 g_qh[MROWS * DIM];
__device__ __nv_bfloat16 g_ql[MROWS * DIM];
__device__ __nv_bfloat16 g_kh[MROWS * DIM];
__device__ __nv_bfloat16 g_kl[MROWS * DIM];
__device__ __nv_bfloat16 g_vh[MROWS * DIM];
__device__ __nv_bfloat16 g_vl[MROWS * DIM];
__device__ __nv_bfloat16 g_xh[MROWS * DIM];
__device__ __nv_bfloat16 g_xl[MROWS * DIM];
__device__ __half g_x16[MROWS * DIM];
__device__ __half g_cx16[MROWS * DIM];
__device__ __nv_bfloat16 g_wqh[DIM * DIM];
__device__ __nv_bfloat16 g_wql[DIM * DIM];
__device__ __nv_bfloat16 g_wkh[DIM * DIM];
__device__ __nv_bfloat16 g_wkl[DIM * DIM];
__device__ __half g_wvh16[DIM * DIM];
__device__ __half g_wvl16[DIM * DIM];
__device__ __half g_woh16[DIM * DIM];
__device__ __half g_wol16[DIM * DIM];

// ---------------------------------------------------------------------------
// Portable PTX helpers
// ---------------------------------------------------------------------------
__device__ __forceinline__ uint32_t smem_u32(const void* p) {
    uint32_t a;
    asm("{ .reg .u64 t; cvta.to.shared.u64 t, %1; cvt.u32.u64 %0, t; }"
        : "=r"(a) : "l"(p));
    return a;
}

#define CP_ASYNC16(dst, src) \
    asm volatile("cp.async.cg.shared.global [%0], [%1], 16;" :: "r"(dst), "l"(src))
#define CP_COMMIT() asm volatile("cp.async.commit_group;" ::: "memory")
#define CP_WAIT(n)  asm volatile("cp.async.wait_group %0;" :: "n"(n) : "memory")

__device__ __forceinline__ void ldsm_x4(uint32_t& r0, uint32_t& r1,
                                        uint32_t& r2, uint32_t& r3, uint32_t addr) {
    asm volatile("ldmatrix.sync.aligned.m8n8.x4.shared.b16 {%0,%1,%2,%3}, [%4];"
                 : "=r"(r0), "=r"(r1), "=r"(r2), "=r"(r3) : "r"(addr));
}

__device__ __forceinline__ void ldsm_x4_t(uint32_t& r0, uint32_t& r1,
                                          uint32_t& r2, uint32_t& r3, uint32_t addr) {
    asm volatile("ldmatrix.sync.aligned.m8n8.x4.trans.shared.b16 {%0,%1,%2,%3}, [%4];"
                 : "=r"(r0), "=r"(r1), "=r"(r2), "=r"(r3) : "r"(addr));
}

__device__ __forceinline__ void mma_bf16(float& c0, float& c1, float& c2, float& c3,
                                         uint32_t a0, uint32_t a1, uint32_t a2, uint32_t a3,
                                         uint32_t b0, uint32_t b1) {
    asm volatile(
        "mma.sync.aligned.m16n8k16.row.col.f32.bf16.bf16.f32 "
        "{%0,%1,%2,%3}, {%4,%5,%6,%7}, {%8,%9}, {%0,%1,%2,%3};"
        : "+f"(c0), "+f"(c1), "+f"(c2), "+f"(c3)
        : "r"(a0), "r"(a1), "r"(a2), "r"(a3), "r"(b0), "r"(b1));
}

__device__ __forceinline__ void mma_fp16(float& c0, float& c1, float& c2, float& c3,
                                         uint32_t a0, uint32_t a1, uint32_t a2, uint32_t a3,
                                         uint32_t b0, uint32_t b1) {
    asm volatile(
        "mma.sync.aligned.m16n8k16.row.col.f32.f16.f16.f32 "
        "{%0,%1,%2,%3}, {%4,%5,%6,%7}, {%8,%9}, {%0,%1,%2,%3};"
        : "+f"(c0), "+f"(c1), "+f"(c2), "+f"(c3)
        : "r"(a0), "r"(a1), "r"(a2), "r"(a3), "r"(b0), "r"(b1));
}

__device__ __forceinline__ uint32_t pack_bf2(__nv_bfloat16 a, __nv_bfloat16 b) {
    __nv_bfloat162 t(a, b);
    return *(uint32_t*)&t;
}

__device__ __forceinline__ void split2(float a, float b, uint32_t& hi, uint32_t& lo) {
    __nv_bfloat16 ha = __float2bfloat16(a), hb = __float2bfloat16(b);
    float ra = a - __bfloat162float(ha);
    float rb = b - __bfloat162float(hb);
    hi = pack_bf2(ha, hb);
    lo = pack_bf2(__float2bfloat16(ra), __float2bfloat16(rb));
}

__device__ __forceinline__ uint32_t pack_h2(float a, float b) {
    __half2 t = __floats2half2_rn(a, b);
    return *(uint32_t*)&t;
}

// fp16 hi/lo split of two floats
__device__ __forceinline__ void split2h(float a, float b, uint32_t& hi, uint32_t& lo) {
    __half ha = __float2half_rn(a), hb = __float2half_rn(b);
    float ra = a - __half2float(ha);
    float rb = b - __half2float(hb);
    __half2 th(ha, hb);
    __half2 tl(__float2half_rn(ra), __float2half_rn(rb));
    hi = *(uint32_t*)&th;
    lo = *(uint32_t*)&tl;
}

// ---------------------------------------------------------------------------
// converts
// ---------------------------------------------------------------------------
// X -> bf16 hi/lo (for Q/K proj) AND single fp16 (for V proj)
__global__ __launch_bounds__(256) void split_x(const float* __restrict__ src,
                                               __nv_bfloat16* __restrict__ hi,
                                               __nv_bfloat16* __restrict__ lo,
                                               __half* __restrict__ h16) {
    int i = (blockIdx.x * 256 + threadIdx.x) * 4;
    float4 x = *(const float4*)(src + i);
    uint32_t h0, l0, h1, l1;
    split2(x.x, x.y, h0, l0);
    split2(x.z, x.w, h1, l1);
    uint32_t* ph = (uint32_t*)(hi + i);
    uint32_t* pl = (uint32_t*)(lo + i);
    uint32_t* p16 = (uint32_t*)(h16 + i);
    ph[0] = h0; ph[1] = h1;
    pl[0] = l0; pl[1] = l1;
    p16[0] = pack_h2(x.x, x.y);
    p16[1] = pack_h2(x.z, x.w);
}

// weights: Wq,Wk -> bf16 hi/lo; Wv,Wo -> fp16 hi/lo
__global__ __launch_bounds__(256) void conv_w4(const float* __restrict__ s0,
                                               const float* __restrict__ s1,
                                               const float* __restrict__ s2,
                                               const float* __restrict__ s3,
                                               __nv_bfloat16* __restrict__ bq_h,
                                               __nv_bfloat16* __restrict__ bq_l,
                                               __nv_bfloat16* __restrict__ bk_h,
                                               __nv_bfloat16* __restrict__ bk_l,
                                               __half* __restrict__ hv_h,
                                               __half* __restrict__ hv_l,
                                               __half* __restrict__ ho_h,
                                               __half* __restrict__ ho_l) {
    int w = blockIdx.y;
    int i = (blockIdx.x * 256 + threadIdx.x) * 4;
    if (w < 2) {
        const float* src = (w == 0) ? s0 : s1;
        __nv_bfloat16* hi = (w == 0) ? bq_h : bk_h;
        __nv_bfloat16* lo = (w == 0) ? bq_l : bk_l;
        float4 x = *(const float4*)(src + i);
        uint32_t h0, l0, h1, l1;
        split2(x.x, x.y, h0, l0);
        split2(x.z, x.w, h1, l1);
        uint32_t* ph = (uint32_t*)(hi + i);
        uint32_t* pl = (uint32_t*)(lo + i);
        ph[0] = h0; ph[1] = h1;
        pl[0] = l0; pl[1] = l1;
    } else {
        const float* src = (w == 2) ? s2 : s3;
        __half* hi = (w == 2) ? hv_h : ho_h;
        __half* lo = (w == 2) ? hv_l : ho_l;
        float4 x = *(const float4*)(src + i);
        uint32_t h0, l0, h1, l1;
        split2h(x.x, x.y, h0, l0);
        split2h(x.z, x.w, h1, l1);
        uint32_t* ph = (uint32_t*)(hi + i);
        uint32_t* pl = (uint32_t*)(lo + i);
        ph[0] = h0; ph[1] = h1;
        pl[0] = l0; pl[1] = l1;
    }
}

// ---------------------------------------------------------------------------
// 3-pass bf16 GEMM (verified R3-R8): C = (Ah+Al)(Bh+Bl)^T, bf16 hi/lo out
// ---------------------------------------------------------------------------
#define GP      40
#define TBYTES  (128 * GP * 2)
#define STAGEB  (4 * TBYTES)
#define NCH     (DIM / 32)

__device__ __forceinline__ void gemm3p_body(const __nv_bfloat16* Ah, const __nv_bfloat16* Al,
                                            const __nv_bfloat16* Bh, const __nv_bfloat16* Bl,
                                            __nv_bfloat16* Ch, __nv_bfloat16* Cl,
                                            int bm, int bn, char* smem) {
    const int tid = threadIdx.x;
    const int wid = tid >> 5;
    const int lane = tid & 31;
    const int wm = (wid & 1) * 64;
    const int wn = (wid >> 1) * 32;
    const uint32_t sbase = smem_u32(smem);

    const char* gAh = (const char*)Ah + (size_t)bm * (DIM * 2);
    const char* gAl = (const char*)Al + (size_t)bm * (DIM * 2);
    const char* gBh = (const char*)Bh + (size_t)bn * (DIM * 2);
    const char* gBl = (const char*)Bl + (size_t)bn * (DIM * 2);

    auto issue = [&](int c, int s) {
        uint32_t st = sbase + s * STAGEB;
        const size_t gk = (size_t)c * 64;
#pragma unroll
        for (int rep = 0; rep < 2; rep++) {
            int t = rep ? (tid + 256) : tid;
            int r = t >> 2;
            int cc = (t & 3) << 4;
            uint32_t dst = st + r * 80 + cc;
            size_t src = (size_t)r * (DIM * 2) + gk + cc;
            CP_ASYNC16(dst,              gAh + src);
            CP_ASYNC16(dst + TBYTES,     gAl + src);
            CP_ASYNC16(dst + 2 * TBYTES, gBh + src);
            CP_ASYNC16(dst + 3 * TBYTES, gBl + src);
        }
    };

    float acc[4][4][4];
#pragma unroll
    for (int i = 0; i < 4; i++)
#pragma unroll
        for (int j = 0; j < 4; j++)
#pragma unroll
            for (int r = 0; r < 4; r++) acc[i][j][r] = 0.0f;

    const int a_r = lane & 15, a_c = (lane >> 4) * 8;
    const int b_r = (lane & 7) + ((lane >> 4) & 1) * 8, b_c = ((lane >> 3) & 1) * 8;

    issue(0, 0);
    CP_COMMIT();

    for (int c = 0; c < NCH; ++c) {
        const int s = c & 1;
        if (c + 1 < NCH) {
            issue(c + 1, s ^ 1);
            CP_COMMIT();
            CP_WAIT(1);
        } else {
            CP_WAIT(0);
        }
        __syncthreads();

        const uint32_t st = sbase + s * STAGEB;
        const uint32_t pAh = st;
        const uint32_t pAl = st + TBYTES;
        const uint32_t pBh = st + 2 * TBYTES;
        const uint32_t pBl = st + 3 * TBYTES;

#pragma unroll
        for (int kk = 0; kk < 32; kk += 16) {
            uint32_t ah[4][4], al[4][4];
#pragma unroll
            for (int mi = 0; mi < 4; mi++) {
                uint32_t off = (uint32_t)((wm + mi * 16 + a_r) * 80 + (kk + a_c) * 2);
                ldsm_x4(ah[mi][0], ah[mi][1], ah[mi][2], ah[mi][3], pAh + off);
                ldsm_x4(al[mi][0], al[mi][1], al[mi][2], al[mi][3], pAl + off);
            }
            uint32_t bh[4][2], bl[4][2];
#pragma unroll
            for (int nb = 0; nb < 2; nb++) {
                uint32_t off = (uint32_t)((wn + nb * 16 + b_r) * 80 + (kk + b_c) * 2);
                uint32_t r0, r1, r2, r3;
                ldsm_x4(r0, r1, r2, r3, pBh + off);
                bh[nb * 2][0] = r0; bh[nb * 2][1] = r1;
                bh[nb * 2 + 1][0] = r2; bh[nb * 2 + 1][1] = r3;
                ldsm_x4(r0, r1, r2, r3, pBl + off);
                bl[nb * 2][0] = r0; bl[nb * 2][1] = r1;
                bl[nb * 2 + 1][0] = r2; bl[nb * 2 + 1][1] = r3;
            }
#pragma unroll
            for (int mi = 0; mi < 4; mi++)
#pragma unroll
                for (int ni = 0; ni < 4; ni++) {
                    mma_bf16(acc[mi][ni][0], acc[mi][ni][1], acc[mi][ni][2], acc[mi][ni][3],
                             ah[mi][0], ah[mi][1], ah[mi][2], ah[mi][3],
                             bh[ni][0], bh[ni][1]);
                    mma_bf16(acc[mi][ni][0], acc[mi][ni][1], acc[mi][ni][2], acc[mi][ni][3],
                             ah[mi][0], ah[mi][1], ah[mi][2], ah[mi][3],
                             bl[ni][0], bl[ni][1]);
                    mma_bf16(acc[mi][ni][0], acc[mi][ni][1], acc[mi][ni][2], acc[mi][ni][3],
                             al[mi][0], al[mi][1], al[mi][2], al[mi][3],
                             bh[ni][0], bh[ni][1]);
                }
        }
        __syncthreads();
    }

    const int er = lane >> 2;
    const int ec = (lane & 3) * 2;
#pragma unroll
    for (int mi = 0; mi < 4; mi++) {
#pragma unroll
        for (int ni = 0; ni < 4; ni++) {
            int col = bn + wn + ni * 8 + ec;
            int row0 = bm + wm + mi * 16 + er;
            int row1 = row0 + 8;
            uint32_t h0, l0, h1, l1;
            split2(acc[mi][ni][0], acc[mi][ni][1], h0, l0);
            split2(acc[mi][ni][2], acc[mi][ni][3], h1, l1);
            *(uint32_t*)(Ch + (size_t)row0 * DIM + col) = h0;
            *(uint32_t*)(Cl + (size_t)row0 * DIM + col) = l0;
            *(uint32_t*)(Ch + (size_t)row1 * DIM + col) = h1;
            *(uint32_t*)(Cl + (size_t)row1 * DIM + col) = l1;
        }
    }
}

__global__ __launch_bounds__(256) void gemm_qk(const __nv_bfloat16* __restrict__ xh,
                                               const __nv_bfloat16* __restrict__ xl,
                                               const __nv_bfloat16* __restrict__ wqh,
                                               const __nv_bfloat16* __restrict__ wql,
                                               const __nv_bfloat16* __restrict__ wkh,
                                               const __nv_bfloat16* __restrict__ wkl,
                                               __nv_bfloat16* __restrict__ qh,
                                               __nv_bfloat16* __restrict__ ql,
                                               __nv_bfloat16* __restrict__ kh,
                                               __nv_bfloat16* __restrict__ kl) {
    extern __shared__ char smem[];
    const __nv_bfloat16* bh = (blockIdx.z == 0) ? wqh : wkh;
    const __nv_bfloat16* bl = (blockIdx.z == 0) ? wql : wkl;
    __nv_bfloat16* oh = (blockIdx.z == 0) ? qh : kh;
    __nv_bfloat16* ol = (blockIdx.z == 0) ? ql : kl;
    gemm3p_body(xh, xl, bh, bl, oh, ol, blockIdx.y * 128, blockIdx.x * 128, smem);
}

// ---------------------------------------------------------------------------
// 2-pass fp16 GEMM: C = A (Bh+Bl)^T. A single fp16; weight rounding cancelled.
// ---------------------------------------------------------------------------
#define H2TILE  10240
#define H2STAGE (3 * H2TILE)
#define H2DYN   (2 * H2STAGE)   // 61440

template <bool BF16OUT>
__device__ __forceinline__ void gemm2p_body(const __half* A, const __half* Bh,
                                            const __half* Bl,
                                            const float* bias, float* C,
                                            __nv_bfloat16* Ch, __nv_bfloat16* Cl,
                                            int bm, int bn, char* smem) {
    const int tid = threadIdx.x;
    const int wid = tid >> 5;
    const int lane = tid & 31;
    const int wm = (wid & 1) * 64;
    const int wn = (wid >> 1) * 32;
    const uint32_t sbase = smem_u32(smem);

    const char* gA  = (const char*)A  + (size_t)bm * (DIM * 2);
    const char* gBh = (const char*)Bh + (size_t)bn * (DIM * 2);
    const char* gBl = (const char*)Bl + (size_t)bn * (DIM * 2);

    auto issue = [&](int c, int s) {
        uint32_t st = sbase + s * H2STAGE;
        const size_t gk = (size_t)c * 64;
#pragma unroll
        for (int rep = 0; rep < 2; rep++) {
            int t = rep ? (tid + 256) : tid;
            int r = t >> 2;
            int cc = (t & 3) << 4;
            uint32_t dst = st + r * 80 + cc;
            size_t src = (size_t)r * (DIM * 2) + gk + cc;
            CP_ASYNC16(dst,              gA + src);
            CP_ASYNC16(dst + H2TILE,     gBh + src);
            CP_ASYNC16(dst + 2 * H2TILE, gBl + src);
        }
    };

    float acc[4][4][4];
#pragma unroll
    for (int i = 0; i < 4; i++)
#pragma unroll
        for (int j = 0; j < 4; j++)
#pragma unroll
            for (int r = 0; r < 4; r++) acc[i][j][r] = 0.0f;

    const int a_r = lane & 15, a_c = (lane >> 4) * 8;
    const int b_r = (lane & 7) + ((lane >> 4) & 1) * 8, b_c = ((lane >> 3) & 1) * 8;

    issue(0, 0);
    CP_COMMIT();

    for (int c = 0; c < NCH; ++c) {
        const int s = c & 1;
        if (c + 1 < NCH) {
            issue(c + 1, s ^ 1);
            CP_COMMIT();
            CP_WAIT(1);
        } else {
            CP_WAIT(0);
        }
        __syncthreads();

        const uint32_t st = sbase + s * H2STAGE;
        const uint32_t pA  = st;
        const uint32_t pBh = st + H2TILE;
        const uint32_t pBl = st + 2 * H2TILE;

#pragma unroll
        for (int kk = 0; kk < 32; kk += 16) {
            uint32_t af[4][4];
#pragma unroll
            for (int mi = 0; mi < 4; mi++) {
                uint32_t off = (uint32_t)((wm + mi * 16 + a_r) * 80 + (kk + a_c) * 2);
                ldsm_x4(af[mi][0], af[mi][1], af[mi][2], af[mi][3], pA + off);
            }
            uint32_t bh[4][2], bl[4][2];
#pragma unroll
            for (int nb = 0; nb < 2; nb++) {
                uint32_t off = (uint32_t)((wn + nb * 16 + b_r) * 80 + (kk + b_c) * 2);
                uint32_t r0, r1, r2, r3;
                ldsm_x4(r0, r1, r2, r3, pBh + off);
                bh[nb * 2][0] = r0; bh[nb * 2][1] = r1;
                bh[nb * 2 + 1][0] = r2; bh[nb * 2 + 1][1] = r3;
                ldsm_x4(r0, r1, r2, r3, pBl + off);
                bl[nb * 2][0] = r0; bl[nb * 2][1] = r1;
                bl[nb * 2 + 1][0] = r2; bl[nb * 2 + 1][1] = r3;
            }
#pragma unroll
            for (int mi = 0; mi < 4; mi++)
#pragma unroll
                for (int ni = 0; ni < 4; ni++) {
                    mma_fp16(acc[mi][ni][0], acc[mi][ni][1], acc[mi][ni][2], acc[mi][ni][3],
                             af[mi][0], af[mi][1], af[mi][2], af[mi][3],
                             bh[ni][0], bh[ni][1]);
                    mma_fp16(acc[mi][ni][0], acc[mi][ni][1], acc[mi][ni][2], acc[mi][ni][3],
                             af[mi][0], af[mi][1], af[mi][2], af[mi][3],
                             bl[ni][0], bl[ni][1]);
                }
        }
        __syncthreads();
    }

    const int er = lane >> 2;
    const int ec = (lane & 3) * 2;
#pragma unroll
    for (int mi = 0; mi < 4; mi++) {
#pragma unroll
        for (int ni = 0; ni < 4; ni++) {
            int col = bn + wn + ni * 8 + ec;
            int row0 = bm + wm + mi * 16 + er;
            int row1 = row0 + 8;
            if (BF16OUT) {
                uint32_t h0, l0, h1, l1;
                split2(acc[mi][ni][0], acc[mi][ni][1], h0, l0);
                split2(acc[mi][ni][2], acc[mi][ni][3], h1, l1);
                *(uint32_t*)(Ch + (size_t)row0 * DIM + col) = h0;
                *(uint32_t*)(Cl + (size_t)row0 * DIM + col) = l0;
                *(uint32_t*)(Ch + (size_t)row1 * DIM + col) = h1;
                *(uint32_t*)(Cl + (size_t)row1 * DIM + col) = l1;
            } else {
                float b0 = bias[col], b1 = bias[col + 1];
                *(float2*)(C + (size_t)row0 * DIM + col) =
                    make_float2(acc[mi][ni][0] + b0, acc[mi][ni][1] + b1);
                *(float2*)(C + (size_t)row1 * DIM + col) =
                    make_float2(acc[mi][ni][2] + b0, acc[mi][ni][3] + b1);
            }
        }
    }
}

__global__ __launch_bounds__(256) void gemm_v(const __half* __restrict__ x16,
                                              const __half* __restrict__ wvh,
                                              const __half* __restrict__ wvl,
                                              __nv_bfloat16* __restrict__ vh,
                                              __nv_bfloat16* __restrict__ vl) {
    extern __shared__ char smem[];
    gemm2p_body<true>(x16, wvh, wvl, nullptr, nullptr, vh, vl,
                      blockIdx.y * 128, blockIdx.x * 128, smem);
}

__global__ __launch_bounds__(256) void gemm_o(const __half* __restrict__ cx,
                                              const __half* __restrict__ woh,
                                              const __half* __restrict__ wol,
                                              const float* __restrict__ bias,
                                              float* __restrict__ C) {
    extern __shared__ char smem[];
    gemm2p_body<false>(cx, woh, wol, bias, C, nullptr, nullptr,
                       blockIdx.y * 128, blockIdx.x * 128, smem);
}

// ---------------------------------------------------------------------------
// HMMA windowed flash attention (verified R8/R9 structure), bf16 hi/lo in,
// fp16 ctx out. 128 threads, 64 queries, pitch 144B, 8-tile arena, 3 CTAs/SM.
// ---------------------------------------------------------------------------
#define APITCH 144
#define ATB    (64 * APITCH)
#define ADYN   (8 * ATB)

__global__ __launch_bounds__(128, 3) void attn_mma(const __nv_bfloat16* __restrict__ Qh,
                                                   const __nv_bfloat16* __restrict__ Ql,
                                                   const __nv_bfloat16* __restrict__ Kh,
                                                   const __nv_bfloat16* __restrict__ Kl,
                                                   const __nv_bfloat16* __restrict__ Vh,
                                                   const __nv_bfloat16* __restrict__ Vl,
                                                   __half* __restrict__ cx) {
    extern __shared__ char smem[];
    const uint32_t s0 = smem_u32(smem);

    const int qb = blockIdx.x * 64;
    const int h = blockIdx.y;
    const int b = blockIdx.z;
    const int tid = threadIdx.x;
    const int warp = tid >> 5;
    const int lane = tid & 31;

    {
        const char* gQh = (const char*)Qh + (((size_t)b * SEQ + qb) * DIM + h * HDIM) * 2;
        const char* gQl = (const char*)Ql + (((size_t)b * SEQ + qb) * DIM + h * HDIM) * 2;
        for (int i = tid; i < 512; i += 128) {
            int r = i >> 3;
            int c = (i & 7) << 4;
            uint32_t dst = s0 + r * APITCH + c;
            size_t src = (size_t)r * (DIM * 2) + c;
            CP_ASYNC16(dst, gQh + src);
            CP_ASYNC16(dst + ATB, gQl + src);
        }
        CP_COMMIT();
        CP_WAIT(0);
        __syncthreads();
    }

    const int a_r = lane & 15, a_c = (lane >> 4) * 8;
    const int b_r = (lane & 7) + ((lane >> 4) & 1) * 8, b_c = ((lane >> 3) & 1) * 8;
    const int v_r = (lane & 7) + ((lane >> 3) & 1) * 8, v_c = ((lane >> 4) & 1) * 8;

    uint32_t qfh[4][4], qfl[4][4];
#pragma unroll
    for (int t = 0; t < 4; t++) {
        uint32_t off = (uint32_t)((warp * 16 + a_r) * APITCH + (t * 16 + a_c) * 2);
        ldsm_x4(qfh[t][0], qfh[t][1], qfh[t][2], qfh[t][3], s0 + off);
        ldsm_x4(qfl[t][0], qfl[t][1], qfl[t][2], qfl[t][3], s0 + ATB + off);
    }
    __syncthreads();

    int kstart = qb - (WIN - 1);
    if (kstart < 0) kstart = 0;
    kstart &= ~63;
    const int ntiles = (qb + 63 - kstart) / 64 + 1;

    auto issueKV = [&](int kt, int s) {
        const size_t base = (((size_t)b * SEQ + kt) * DIM + h * HDIM) * 2;
        const char* pKh = (const char*)Kh + base;
        const char* pKl = (const char*)Kl + base;
        const char* pVh = (const char*)Vh + base;
        const char* pVl = (const char*)Vl + base;
        uint32_t sb = s0 + s * 4 * ATB;
        for (int i = tid; i < 512; i += 128) {
            int r = i >> 3;
            int c = (i & 7) << 4;
            uint32_t dst = sb + r * APITCH + c;
            size_t src = (size_t)r * (DIM * 2) + c;
            CP_ASYNC16(dst,           pKh + src);
            CP_ASYNC16(dst + ATB,     pKl + src);
            CP_ASYNC16(dst + 2 * ATB, pVh + src);
            CP_ASYNC16(dst + 3 * ATB, pVl + src);
        }
    };

    issueKV(kstart, 0);
    CP_COMMIT();
    if (ntiles > 1) {
        issueKV(kstart + 64, 1);
        CP_COMMIT();
    }

    float m0 = -1e30f, m1 = -1e30f, l0 = 0.0f, l1 = 0.0f;
    float o[8][4];
#pragma unroll
    for (int j = 0; j < 8; j++)
#pragma unroll
        for (int r = 0; r < 4; r++) o[j][r] = 0.0f;

    const int row0 = qb + warp * 16 + (lane >> 2);
    const int row1 = row0 + 8;

    for (int it = 0; it < ntiles; ++it) {
        const int kt = kstart + it * 64;
        const int s = it & 1;
        if (it + 1 < ntiles) { CP_WAIT(1); } else { CP_WAIT(0); }
        __syncthreads();

        const uint32_t sKh = s0 + s * 4 * ATB;
        const uint32_t sKl = sKh + ATB;
        const uint32_t sVh = sKh + 2 * ATB;
        const uint32_t sVl = sKh + 3 * ATB;

        float acc[8][4];
#pragma unroll
        for (int j = 0; j < 8; j++)
#pragma unroll
            for (int r = 0; r < 4; r++) acc[j][r] = 0.0f;

#pragma unroll
        for (int t = 0; t < 4; t++) {
#pragma unroll
            for (int g = 0; g < 4; g++) {
                uint32_t off = (uint32_t)((g * 16 + b_r) * APITCH + (t * 16 + b_c) * 2);
                uint32_t kh0, kh1, kh2, kh3, kl0, kl1, kl2, kl3;
                ldsm_x4(kh0, kh1, kh2, kh3, sKh + off);
                ldsm_x4(kl0, kl1, kl2, kl3, sKl + off);
                int n0 = 2 * g, n1 = 2 * g + 1;
                mma_bf16(acc[n0][0], acc[n0][1], acc[n0][2], acc[n0][3],
                         qfh[t][0], qfh[t][1], qfh[t][2], qfh[t][3], kh0, kh1);
                mma_bf16(acc[n1][0], acc[n1][1], acc[n1][2], acc[n1][3],
                         qfh[t][0], qfh[t][1], qfh[t][2], qfh[t][3], kh2, kh3);
                mma_bf16(acc[n0][0], acc[n0][1], acc[n0][2], acc[n0][3],
                         qfh[t][0], qfh[t][1], qfh[t][2], qfh[t][3], kl0, kl1);
                mma_bf16(acc[n1][0], acc[n1][1], acc[n1][2], acc[n1][3],
                         qfh[t][0], qfh[t][1], qfh[t][2], qfh[t][3], kl2, kl3);
                mma_bf16(acc[n0][0], acc[n0][1], acc[n0][2], acc[n0][3],
                         qfl[t][0], qfl[t][1], qfl[t][2], qfl[t][3], kh0, kh1);
                mma_bf16(acc[n1][0], acc[n1][1], acc[n1][2], acc[n1][3],
                         qfl[t][0], qfl[t][1], qfl[t][2], qfl[t][3], kh2, kh3);
            }
        }

        float tmax0 = -1e30f, tmax1 = -1e30f;
#pragma unroll
        for (int j = 0; j < 8; j++) {
            int colb = kt + 8 * j + 2 * (lane & 3);
#pragma unroll
            for (int e = 0; e < 2; e++) {
                int col = colb + e;
                bool v0 = (col <= row0) && (row0 - col < WIN);
                bool v1 = (col <= row1) && (row1 - col < WIN);
                if (!v0) acc[j][e] = -1e30f;
                if (!v1) acc[j][2 + e] = -1e30f;
            }
            tmax0 = fmaxf(tmax0, fmaxf(acc[j][0], acc[j][1]));
            tmax1 = fmaxf(tmax1, fmaxf(acc[j][2], acc[j][3]));
        }
#pragma unroll
        for (int off = 1; off <= 2; off <<= 1) {
            tmax0 = fmaxf(tmax0, __shfl_xor_sync(0xffffffffu, tmax0, off));
            tmax1 = fmaxf(tmax1, __shfl_xor_sync(0xffffffffu, tmax1, off));
        }
        float mn0 = fmaxf(m0, tmax0);
        float mn1 = fmaxf(m1, tmax1);

        float rs0 = 0.0f, rs1 = 0.0f;
#pragma unroll
        for (int j = 0; j < 8; j++) {
            acc[j][0] = __expf(acc[j][0] - mn0);
            acc[j][1] = __expf(acc[j][1] - mn0);
            acc[j][2] = __expf(acc[j][2] - mn1);
            acc[j][3] = __expf(acc[j][3] - mn1);
            rs0 += acc[j][0] + acc[j][1];
            rs1 += acc[j][2] + acc[j][3];
        }
#pragma unroll
        for (int off = 1; off <= 2; off <<= 1) {
            rs0 += __shfl_xor_sync(0xffffffffu, rs0, off);
            rs1 += __shfl_xor_sync(0xffffffffu, rs1, off);
        }
        float corr0 = __expf(m0 - mn0);
        float corr1 = __expf(m1 - mn1);
        l0 = l0 * corr0 + rs0;
        l1 = l1 * corr1 + rs1;
        m0 = mn0;
        m1 = mn1;
#pragma unroll
        for (int j = 0; j < 8; j++) {
            o[j][0] *= corr0;
            o[j][1] *= corr0;
            o[j][2] *= corr1;
            o[j][3] *= corr1;
        }

#pragma unroll
        for (int t = 0; t < 4; t++) {
            uint32_t ph[4], pl[4];
            split2(acc[2 * t][0], acc[2 * t][1], ph[0], pl[0]);
            split2(acc[2 * t][2], acc[2 * t][3], ph[1], pl[1]);
            split2(acc[2 * t + 1][0], acc[2 * t + 1][1], ph[2], pl[2]);
            split2(acc[2 * t + 1][2], acc[2 * t + 1][3], ph[3], pl[3]);
#pragma unroll
            for (int g = 0; g < 4; g++) {
                uint32_t off = (uint32_t)((t * 16 + v_r) * APITCH + (g * 16 + v_c) * 2);
                uint32_t vh0, vh1, vh2, vh3, vl0, vl1, vl2, vl3;
                ldsm_x4_t(vh0, vh1, vh2, vh3, sVh + off);
                ldsm_x4_t(vl0, vl1, vl2, vl3, sVl + off);
                int n0 = 2 * g, n1 = 2 * g + 1;
                mma_bf16(o[n0][0], o[n0][1], o[n0][2], o[n0][3],
                         ph[0], ph[1], ph[2], ph[3], vh0, vh1);
                mma_bf16(o[n1][0], o[n1][1], o[n1][2], o[n1][3],
                         ph[0], ph[1], ph[2], ph[3], vh2, vh3);
                mma_bf16(o[n0][0], o[n0][1], o[n0][2], o[n0][3],
                         ph[0], ph[1], ph[2], ph[3], vl0, vl1);
                mma_bf16(o[n1][0], o[n1][1], o[n1][2], o[n1][3],
                         ph[0], ph[1], ph[2], ph[3], vl2, vl3);
                mma_bf16(o[n0][0], o[n0][1], o[n0][2], o[n0][3],
                         pl[0], pl[1], pl[2], pl[3], vh0, vh1);
                mma_bf16(o[n1][0], o[n1][1], o[n1][2], o[n1][3],
                         pl[0], pl[1], pl[2], pl[3], vh2, vh3);
            }
        }
        __syncthreads();
        if (it + 2 < ntiles) {
            issueKV(kstart + (it + 2) * 64, s);
            CP_COMMIT();
        }
    }

    float inv0 = 1.0f / l0;
    float inv1 = 1.0f / l1;
    const size_t tok0 = (size_t)b * SEQ + row0;
    const size_t tok1 = (size_t)b * SEQ + row1;
    const int colbase = h * HDIM + 2 * (lane & 3);
#pragma unroll
    for (int j = 0; j < 8; j++) {
        int col = colbase + 8 * j;
        *(uint32_t*)(cx + tok0 * DIM + col) = pack_h2(o[j][0] * inv0, o[j][1] * inv0);
        *(uint32_t*)(cx + tok1 * DIM + col) = pack_h2(o[j][2] * inv1, o[j][3] * inv1);
    }
}

// ---------------------------------------------------------------------------
extern "C" void kernel_launch(void* const* d_in, const int* in_sizes, int n_in,
                              void* d_out, int out_size) {
    (void)in_sizes; (void)n_in; (void)out_size;
    const float* X  = (const float*)d_in[0];
    const float* Wq = (const float*)d_in[1];
    const float* Wk = (const float*)d_in[2];
    const float* Wv = (const float*)d_in[3];
    const float* Wo = (const float*)d_in[4];
    const float* bo = (const float*)d_in[5];
    float* out = (float*)d_out;

    __nv_bfloat16 *qh, *ql, *kh, *kl, *vh, *vl, *xh, *xl;
    __nv_bfloat16 *wqh, *wql, *wkh, *wkl;
    __half *x16, *cx16, *wvh16, *wvl16, *woh16, *wol16;
    cudaGetSymbolAddress((void**)&qh, g_qh);
    cudaGetSymbolAddress((void**)&ql, g_ql);
    cudaGetSymbolAddress((void**)&kh, g_kh);
    cudaGetSymbolAddress((void**)&kl, g_kl);
    cudaGetSymbolAddress((void**)&vh, g_vh);
    cudaGetSymbolAddress((void**)&vl, g_vl);
    cudaGetSymbolAddress((void**)&xh, g_xh);
    cudaGetSymbolAddress((void**)&xl, g_xl);
    cudaGetSymbolAddress((void**)&x16, g_x16);
    cudaGetSymbolAddress((void**)&cx16, g_cx16);
    cudaGetSymbolAddress((void**)&wqh, g_wqh);
    cudaGetSymbolAddress((void**)&wql, g_wql);
    cudaGetSymbolAddress((void**)&wkh, g_wkh);
    cudaGetSymbolAddress((void**)&wkl, g_wkl);
    cudaGetSymbolAddress((void**)&wvh16, g_wvh16);
    cudaGetSymbolAddress((void**)&wvl16, g_wvl16);
    cudaGetSymbolAddress((void**)&woh16, g_woh16);
    cudaGetSymbolAddress((void**)&wol16, g_wol16);

    const int DYN3 = 2 * STAGEB;
    cudaFuncSetAttribute(gemm_qk, cudaFuncAttributeMaxDynamicSharedMemorySize, DYN3);
    cudaFuncSetAttribute(gemm_v,  cudaFuncAttributeMaxDynamicSharedMemorySize, H2DYN);
    cudaFuncSetAttribute(gemm_o,  cudaFuncAttributeMaxDynamicSharedMemorySize, H2DYN);
    cudaFuncSetAttribute(attn_mma, cudaFuncAttributeMaxDynamicSharedMemorySize, ADYN);

    const int nX = MROWS * DIM;
    const int nW = DIM * DIM;

    split_x<<<nX / 1024, 256>>>(X, xh, xl, x16);
    dim3 wgrid(nW / 1024, 4);
    conv_w4<<<wgrid, 256>>>(Wq, Wk, Wv, Wo,
                            wqh, wql, wkh, wkl, wvh16, wvl16, woh16, wol16);

    dim3 qk_grid(DIM / 128, MROWS / 128, 2);
    gemm_qk<<<qk_grid, 256, DYN3>>>(xh, xl, wqh, wql, wkh, wkl, qh, ql, kh, kl);

    dim3 vgrid(DIM / 128, MROWS / 128);
    gemm_v<<<vgrid, 256, H2DYN>>>(x16, wvh16, wvl16, vh, vl);

    dim3 attn_grid(SEQ / 64, NHEAD, BATCH);
    attn_mma<<<attn_grid, 128, ADYN>>>(qh, ql, kh, kl, vh, vl, cx16);

    gemm_o<<<vgrid, 256, H2DYN>>>(cx16, woh16, wol16, bo, out);
}

// round 13
// speedup vs baseline: 1.1762x; 1.0002x over previous
#include <cuda_runtime.h>
#include <cuda_bf16.h>
#include <cuda_fp16.h>
#include <stdint.h>

// Problem constants
#define BATCH 4
#define SEQ   2048
#define DIM   1024
#define NHEAD 16
#define HDIM  64
#define WIN   256
#define MROWS (BATCH * SEQ)   // 8192

// ---------------------------------------------------------------------------
// Scratch (device globals: allocation-free rule)
// ---------------------------------------------------------------------------
__device__ __nv_bfloat16 g_qh[MROWS * DIM];
__device__ __nv_bfloat16 g_ql[MROWS * DIM];
__device__ __nv_bfloat16 g_kh[MROWS * DIM];
__device__ __nv_bfloat16 g_kl[MROWS * DIM];
__device__ __nv_bfloat16 g_vh[MROWS * DIM];
__device__ __nv_bfloat16 g_vl[MROWS * DIM];
__device__ __nv_bfloat16 g_xh[MROWS * DIM];
__device__ __nv_bfloat16 g_xl[MROWS * DIM];
__device__ __half g_x16[MROWS * DIM];
__device__ __half g_cx16[MROWS * DIM];
__device__ __nv_bfloat16 g_wqh[DIM * DIM];
__device__ __nv_bfloat16 g_wql[DIM * DIM];
__device__ __nv_bfloat16 g_wkh[DIM * DIM];
__device__ __nv_bfloat16 g_wkl[DIM * DIM];
__device__ __half g_wvh16[DIM * DIM];
__device__ __half g_wvl16[DIM * DIM];
__device__ __half g_woh16[DIM * DIM];
__device__ __half g_wol16[DIM * DIM];

// ---------------------------------------------------------------------------
// Portable PTX helpers
// ---------------------------------------------------------------------------
__device__ __forceinline__ uint32_t smem_u32(const void* p) {
    uint32_t a;
    asm("{ .reg .u64 t; cvta.to.shared.u64 t, %1; cvt.u32.u64 %0, t; }"
        : "=r"(a) : "l"(p));
    return a;
}

#define CP_ASYNC16(dst, src) \
    asm volatile("cp.async.cg.shared.global [%0], [%1], 16;" :: "r"(dst), "l"(src))
#define CP_COMMIT() asm volatile("cp.async.commit_group;" ::: "memory")
#define CP_WAIT(n)  asm volatile("cp.async.wait_group %0;" :: "n"(n) : "memory")

__device__ __forceinline__ void ldsm_x4(uint32_t& r0, uint32_t& r1,
                                        uint32_t& r2, uint32_t& r3, uint32_t addr) {
    asm volatile("ldmatrix.sync.aligned.m8n8.x4.shared.b16 {%0,%1,%2,%3}, [%4];"
                 : "=r"(r0), "=r"(r1), "=r"(r2), "=r"(r3) : "r"(addr));
}

__device__ __forceinline__ void ldsm_x4_t(uint32_t& r0, uint32_t& r1,
                                          uint32_t& r2, uint32_t& r3, uint32_t addr) {
    asm volatile("ldmatrix.sync.aligned.m8n8.x4.trans.shared.b16 {%0,%1,%2,%3}, [%4];"
                 : "=r"(r0), "=r"(r1), "=r"(r2), "=r"(r3) : "r"(addr));
}

__device__ __forceinline__ void mma_bf16(float& c0, float& c1, float& c2, float& c3,
                                         uint32_t a0, uint32_t a1, uint32_t a2, uint32_t a3,
                                         uint32_t b0, uint32_t b1) {
    asm volatile(
        "mma.sync.aligned.m16n8k16.row.col.f32.bf16.bf16.f32 "
        "{%0,%1,%2,%3}, {%4,%5,%6,%7}, {%8,%9}, {%0,%1,%2,%3};"
        : "+f"(c0), "+f"(c1), "+f"(c2), "+f"(c3)
        : "r"(a0), "r"(a1), "r"(a2), "r"(a3), "r"(b0), "r"(b1));
}

__device__ __forceinline__ void mma_fp16(float& c0, float& c1, float& c2, float& c3,
                                         uint32_t a0, uint32_t a1, uint32_t a2, uint32_t a3,
                                         uint32_t b0, uint32_t b1) {
    asm volatile(
        "mma.sync.aligned.m16n8k16.row.col.f32.f16.f16.f32 "
        "{%0,%1,%2,%3}, {%4,%5,%6,%7}, {%8,%9}, {%0,%1,%2,%3};"
        : "+f"(c0), "+f"(c1), "+f"(c2), "+f"(c3)
        : "r"(a0), "r"(a1), "r"(a2), "r"(a3), "r"(b0), "r"(b1));
}

__device__ __forceinline__ uint32_t pack_bf2(__nv_bfloat16 a, __nv_bfloat16 b) {
    __nv_bfloat162 t(a, b);
    return *(uint32_t*)&t;
}

__device__ __forceinline__ void split2(float a, float b, uint32_t& hi, uint32_t& lo) {
    __nv_bfloat16 ha = __float2bfloat16(a), hb = __float2bfloat16(b);
    float ra = a - __bfloat162float(ha);
    float rb = b - __bfloat162float(hb);
    hi = pack_bf2(ha, hb);
    lo = pack_bf2(__float2bfloat16(ra), __float2bfloat16(rb));
}

__device__ __forceinline__ uint32_t pack_h2(float a, float b) {
    __half2 t = __floats2half2_rn(a, b);
    return *(uint32_t*)&t;
}

// fp16 hi/lo split of two floats
__device__ __forceinline__ void split2h(float a, float b, uint32_t& hi, uint32_t& lo) {
    __half ha = __float2half_rn(a), hb = __float2half_rn(b);
    float ra = a - __half2float(ha);
    float rb = b - __half2float(hb);
    __half2 th(ha, hb);
    __half2 tl(__float2half_rn(ra), __float2half_rn(rb));
    hi = *(uint32_t*)&th;
    lo = *(uint32_t*)&tl;
}

// ---------------------------------------------------------------------------
// converts
// ---------------------------------------------------------------------------
// X -> bf16 hi/lo (for Q/K proj) AND single fp16 (for V proj)
__global__ __launch_bounds__(256) void split_x(const float* __restrict__ src,
                                               __nv_bfloat16* __restrict__ hi,
                                               __nv_bfloat16* __restrict__ lo,
                                               __half* __restrict__ h16) {
    int i = (blockIdx.x * 256 + threadIdx.x) * 4;
    float4 x = *(const float4*)(src + i);
    uint32_t h0, l0, h1, l1;
    split2(x.x, x.y, h0, l0);
    split2(x.z, x.w, h1, l1);
    uint32_t* ph = (uint32_t*)(hi + i);
    uint32_t* pl = (uint32_t*)(lo + i);
    uint32_t* p16 = (uint32_t*)(h16 + i);
    ph[0] = h0; ph[1] = h1;
    pl[0] = l0; pl[1] = l1;
    p16[0] = pack_h2(x.x, x.y);
    p16[1] = pack_h2(x.z, x.w);
}

// weights: Wq,Wk -> bf16 hi/lo; Wv,Wo -> fp16 hi/lo
__global__ __launch_bounds__(256) void conv_w4(const float* __restrict__ s0,
                                               const float* __restrict__ s1,
                                               const float* __restrict__ s2,
                                               const float* __restrict__ s3,
                                               __nv_bfloat16* __restrict__ bq_h,
                                               __nv_bfloat16* __restrict__ bq_l,
                                               __nv_bfloat16* __restrict__ bk_h,
                                               __nv_bfloat16* __restrict__ bk_l,
                                               __half* __restrict__ hv_h,
                                               __half* __restrict__ hv_l,
                                               __half* __restrict__ ho_h,
                                               __half* __restrict__ ho_l) {
    int w = blockIdx.y;
    int i = (blockIdx.x * 256 + threadIdx.x) * 4;
    if (w < 2) {
        const float* src = (w == 0) ? s0 : s1;
        __nv_bfloat16* hi = (w == 0) ? bq_h : bk_h;
        __nv_bfloat16* lo = (w == 0) ? bq_l : bk_l;
        float4 x = *(const float4*)(src + i);
        uint32_t h0, l0, h1, l1;
        split2(x.x, x.y, h0, l0);
        split2(x.z, x.w, h1, l1);
        uint32_t* ph = (uint32_t*)(hi + i);
        uint32_t* pl = (uint32_t*)(lo + i);
        ph[0] = h0; ph[1] = h1;
        pl[0] = l0; pl[1] = l1;
    } else {
        const float* src = (w == 2) ? s2 : s3;
        __half* hi = (w == 2) ? hv_h : ho_h;
        __half* lo = (w == 2) ? hv_l : ho_l;
        float4 x = *(const float4*)(src + i);
        uint32_t h0, l0, h1, l1;
        split2h(x.x, x.y, h0, l0);
        split2h(x.z, x.w, h1, l1);
        uint32_t* ph = (uint32_t*)(hi + i);
        uint32_t* pl = (uint32_t*)(lo + i);
        ph[0] = h0; ph[1] = h1;
        pl[0] = l0; pl[1] = l1;
    }
}

// ---------------------------------------------------------------------------
// 3-pass bf16 GEMM (verified R3-R8): C = (Ah+Al)(Bh+Bl)^T, bf16 hi/lo out
// ---------------------------------------------------------------------------
#define GP      40
#define TBYTES  (128 * GP * 2)
#define STAGEB  (4 * TBYTES)
#define NCH     (DIM / 32)

__device__ __forceinline__ void gemm3p_body(const __nv_bfloat16* Ah, const __nv_bfloat16* Al,
                                            const __nv_bfloat16* Bh, const __nv_bfloat16* Bl,
                                            __nv_bfloat16* Ch, __nv_bfloat16* Cl,
                                            int bm, int bn, char* smem) {
    const int tid = threadIdx.x;
    const int wid = tid >> 5;
    const int lane = tid & 31;
    const int wm = (wid & 1) * 64;
    const int wn = (wid >> 1) * 32;
    const uint32_t sbase = smem_u32(smem);

    const char* gAh = (const char*)Ah + (size_t)bm * (DIM * 2);
    const char* gAl = (const char*)Al + (size_t)bm * (DIM * 2);
    const char* gBh = (const char*)Bh + (size_t)bn * (DIM * 2);
    const char* gBl = (const char*)Bl + (size_t)bn * (DIM * 2);

    auto issue = [&](int c, int s) {
        uint32_t st = sbase + s * STAGEB;
        const size_t gk = (size_t)c * 64;
#pragma unroll
        for (int rep = 0; rep < 2; rep++) {
            int t = rep ? (tid + 256) : tid;
            int r = t >> 2;
            int cc = (t & 3) << 4;
            uint32_t dst = st + r * 80 + cc;
            size_t src = (size_t)r * (DIM * 2) + gk + cc;
            CP_ASYNC16(dst,              gAh + src);
            CP_ASYNC16(dst + TBYTES,     gAl + src);
            CP_ASYNC16(dst + 2 * TBYTES, gBh + src);
            CP_ASYNC16(dst + 3 * TBYTES, gBl + src);
        }
    };

    float acc[4][4][4];
#pragma unroll
    for (int i = 0; i < 4; i++)
#pragma unroll
        for (int j = 0; j < 4; j++)
#pragma unroll
            for (int r = 0; r < 4; r++) acc[i][j][r] = 0.0f;

    const int a_r = lane & 15, a_c = (lane >> 4) * 8;
    const int b_r = (lane & 7) + ((lane >> 4) & 1) * 8, b_c = ((lane >> 3) & 1) * 8;

    issue(0, 0);
    CP_COMMIT();

    for (int c = 0; c < NCH; ++c) {
        const int s = c & 1;
        if (c + 1 < NCH) {
            issue(c + 1, s ^ 1);
            CP_COMMIT();
            CP_WAIT(1);
        } else {
            CP_WAIT(0);
        }
        __syncthreads();

        const uint32_t st = sbase + s * STAGEB;
        const uint32_t pAh = st;
        const uint32_t pAl = st + TBYTES;
        const uint32_t pBh = st + 2 * TBYTES;
        const uint32_t pBl = st + 3 * TBYTES;

#pragma unroll
        for (int kk = 0; kk < 32; kk += 16) {
            uint32_t ah[4][4], al[4][4];
#pragma unroll
            for (int mi = 0; mi < 4; mi++) {
                uint32_t off = (uint32_t)((wm + mi * 16 + a_r) * 80 + (kk + a_c) * 2);
                ldsm_x4(ah[mi][0], ah[mi][1], ah[mi][2], ah[mi][3], pAh + off);
                ldsm_x4(al[mi][0], al[mi][1], al[mi][2], al[mi][3], pAl + off);
            }
            uint32_t bh[4][2], bl[4][2];
#pragma unroll
            for (int nb = 0; nb < 2; nb++) {
                uint32_t off = (uint32_t)((wn + nb * 16 + b_r) * 80 + (kk + b_c) * 2);
                uint32_t r0, r1, r2, r3;
                ldsm_x4(r0, r1, r2, r3, pBh + off);
                bh[nb * 2][0] = r0; bh[nb * 2][1] = r1;
                bh[nb * 2 + 1][0] = r2; bh[nb * 2 + 1][1] = r3;
                ldsm_x4(r0, r1, r2, r3, pBl + off);
                bl[nb * 2][0] = r0; bl[nb * 2][1] = r1;
                bl[nb * 2 + 1][0] = r2; bl[nb * 2 + 1][1] = r3;
            }
#pragma unroll
            for (int mi = 0; mi < 4; mi++)
#pragma unroll
                for (int ni = 0; ni < 4; ni++) {
                    mma_bf16(acc[mi][ni][0], acc[mi][ni][1], acc[mi][ni][2], acc[mi][ni][3],
                             ah[mi][0], ah[mi][1], ah[mi][2], ah[mi][3],
                             bh[ni][0], bh[ni][1]);
                    mma_bf16(acc[mi][ni][0], acc[mi][ni][1], acc[mi][ni][2], acc[mi][ni][3],
                             ah[mi][0], ah[mi][1], ah[mi][2], ah[mi][3],
                             bl[ni][0], bl[ni][1]);
                    mma_bf16(acc[mi][ni][0], acc[mi][ni][1], acc[mi][ni][2], acc[mi][ni][3],
                             al[mi][0], al[mi][1], al[mi][2], al[mi][3],
                             bh[ni][0], bh[ni][1]);
                }
        }
        __syncthreads();
    }

    const int er = lane >> 2;
    const int ec = (lane & 3) * 2;
#pragma unroll
    for (int mi = 0; mi < 4; mi++) {
#pragma unroll
        for (int ni = 0; ni < 4; ni++) {
            int col = bn + wn + ni * 8 + ec;
            int row0 = bm + wm + mi * 16 + er;
            int row1 = row0 + 8;
            uint32_t h0, l0, h1, l1;
            split2(acc[mi][ni][0], acc[mi][ni][1], h0, l0);
            split2(acc[mi][ni][2], acc[mi][ni][3], h1, l1);
            *(uint32_t*)(Ch + (size_t)row0 * DIM + col) = h0;
            *(uint32_t*)(Cl + (size_t)row0 * DIM + col) = l0;
            *(uint32_t*)(Ch + (size_t)row1 * DIM + col) = h1;
            *(uint32_t*)(Cl + (size_t)row1 * DIM + col) = l1;
        }
    }
}

__global__ __launch_bounds__(256) void gemm_qk(const __nv_bfloat16* __restrict__ xh,
                                               const __nv_bfloat16* __restrict__ xl,
                                               const __nv_bfloat16* __restrict__ wqh,
                                               const __nv_bfloat16* __restrict__ wql,
                                               const __nv_bfloat16* __restrict__ wkh,
                                               const __nv_bfloat16* __restrict__ wkl,
                                               __nv_bfloat16* __restrict__ qh,
                                               __nv_bfloat16* __restrict__ ql,
                                               __nv_bfloat16* __restrict__ kh,
                                               __nv_bfloat16* __restrict__ kl) {
    extern __shared__ char smem[];
    const __nv_bfloat16* bh = (blockIdx.z == 0) ? wqh : wkh;
    const __nv_bfloat16* bl = (blockIdx.z == 0) ? wql : wkl;
    __nv_bfloat16* oh = (blockIdx.z == 0) ? qh : kh;
    __nv_bfloat16* ol = (blockIdx.z == 0) ? ql : kl;
    gemm3p_body(xh, xl, bh, bl, oh, ol, blockIdx.y * 128, blockIdx.x * 128, smem);
}

// ---------------------------------------------------------------------------
// 2-pass fp16 GEMM: C = A (Bh+Bl)^T. A single fp16; weight rounding cancelled.
// ---------------------------------------------------------------------------
#define H2TILE  10240
#define H2STAGE (3 * H2TILE)
#define H2DYN   (2 * H2STAGE)   // 61440

template <bool BF16OUT>
__device__ __forceinline__ void gemm2p_body(const __half* A, const __half* Bh,
                                            const __half* Bl,
                                            const float* bias, float* C,
                                            __nv_bfloat16* Ch, __nv_bfloat16* Cl,
                                            int bm, int bn, char* smem) {
    const int tid = threadIdx.x;
    const int wid = tid >> 5;
    const int lane = tid & 31;
    const int wm = (wid & 1) * 64;
    const int wn = (wid >> 1) * 32;
    const uint32_t sbase = smem_u32(smem);

    const char* gA  = (const char*)A  + (size_t)bm * (DIM * 2);
    const char* gBh = (const char*)Bh + (size_t)bn * (DIM * 2);
    const char* gBl = (const char*)Bl + (size_t)bn * (DIM * 2);

    auto issue = [&](int c, int s) {
        uint32_t st = sbase + s * H2STAGE;
        const size_t gk = (size_t)c * 64;
#pragma unroll
        for (int rep = 0; rep < 2; rep++) {
            int t = rep ? (tid + 256) : tid;
            int r = t >> 2;
            int cc = (t & 3) << 4;
            uint32_t dst = st + r * 80 + cc;
            size_t src = (size_t)r * (DIM * 2) + gk + cc;
            CP_ASYNC16(dst,              gA + src);
            CP_ASYNC16(dst + H2TILE,     gBh + src);
            CP_ASYNC16(dst + 2 * H2TILE, gBl + src);
        }
    };

    float acc[4][4][4];
#pragma unroll
    for (int i = 0; i < 4; i++)
#pragma unroll
        for (int j = 0; j < 4; j++)
#pragma unroll
            for (int r = 0; r < 4; r++) acc[i][j][r] = 0.0f;

    const int a_r = lane & 15, a_c = (lane >> 4) * 8;
    const int b_r = (lane & 7) + ((lane >> 4) & 1) * 8, b_c = ((lane >> 3) & 1) * 8;

    issue(0, 0);
    CP_COMMIT();

    for (int c = 0; c < NCH; ++c) {
        const int s = c & 1;
        if (c + 1 < NCH) {
            issue(c + 1, s ^ 1);
            CP_COMMIT();
            CP_WAIT(1);
        } else {
            CP_WAIT(0);
        }
        __syncthreads();

        const uint32_t st = sbase + s * H2STAGE;
        const uint32_t pA  = st;
        const uint32_t pBh = st + H2TILE;
        const uint32_t pBl = st + 2 * H2TILE;

#pragma unroll
        for (int kk = 0; kk < 32; kk += 16) {
            uint32_t af[4][4];
#pragma unroll
            for (int mi = 0; mi < 4; mi++) {
                uint32_t off = (uint32_t)((wm + mi * 16 + a_r) * 80 + (kk + a_c) * 2);
                ldsm_x4(af[mi][0], af[mi][1], af[mi][2], af[mi][3], pA + off);
            }
            uint32_t bh[4][2], bl[4][2];
#pragma unroll
            for (int nb = 0; nb < 2; nb++) {
                uint32_t off = (uint32_t)((wn + nb * 16 + b_r) * 80 + (kk + b_c) * 2);
                uint32_t r0, r1, r2, r3;
                ldsm_x4(r0, r1, r2, r3, pBh + off);
                bh[nb * 2][0] = r0; bh[nb * 2][1] = r1;
                bh[nb * 2 + 1][0] = r2; bh[nb * 2 + 1][1] = r3;
                ldsm_x4(r0, r1, r2, r3, pBl + off);
                bl[nb * 2][0] = r0; bl[nb * 2][1] = r1;
                bl[nb * 2 + 1][0] = r2; bl[nb * 2 + 1][1] = r3;
            }
#pragma unroll
            for (int mi = 0; mi < 4; mi++)
#pragma unroll
                for (int ni = 0; ni < 4; ni++) {
                    mma_fp16(acc[mi][ni][0], acc[mi][ni][1], acc[mi][ni][2], acc[mi][ni][3],
                             af[mi][0], af[mi][1], af[mi][2], af[mi][3],
                             bh[ni][0], bh[ni][1]);
                    mma_fp16(acc[mi][ni][0], acc[mi][ni][1], acc[mi][ni][2], acc[mi][ni][3],
                             af[mi][0], af[mi][1], af[mi][2], af[mi][3],
                             bl[ni][0], bl[ni][1]);
                }
        }
        __syncthreads();
    }

    const int er = lane >> 2;
    const int ec = (lane & 3) * 2;
#pragma unroll
    for (int mi = 0; mi < 4; mi++) {
#pragma unroll
        for (int ni = 0; ni < 4; ni++) {
            int col = bn + wn + ni * 8 + ec;
            int row0 = bm + wm + mi * 16 + er;
            int row1 = row0 + 8;
            if (BF16OUT) {
                uint32_t h0, l0, h1, l1;
                split2(acc[mi][ni][0], acc[mi][ni][1], h0, l0);
                split2(acc[mi][ni][2], acc[mi][ni][3], h1, l1);
                *(uint32_t*)(Ch + (size_t)row0 * DIM + col) = h0;
                *(uint32_t*)(Cl + (size_t)row0 * DIM + col) = l0;
                *(uint32_t*)(Ch + (size_t)row1 * DIM + col) = h1;
                *(uint32_t*)(Cl + (size_t)row1 * DIM + col) = l1;
            } else {
                float b0 = bias[col], b1 = bias[col + 1];
                *(float2*)(C + (size_t)row0 * DIM + col) =
                    make_float2(acc[mi][ni][0] + b0, acc[mi][ni][1] + b1);
                *(float2*)(C + (size_t)row1 * DIM + col) =
                    make_float2(acc[mi][ni][2] + b0, acc[mi][ni][3] + b1);
            }
        }
    }
}

__global__ __launch_bounds__(256) void gemm_v(const __half* __restrict__ x16,
                                              const __half* __restrict__ wvh,
                                              const __half* __restrict__ wvl,
                                              __nv_bfloat16* __restrict__ vh,
                                              __nv_bfloat16* __restrict__ vl) {
    extern __shared__ char smem[];
    gemm2p_body<true>(x16, wvh, wvl, nullptr, nullptr, vh, vl,
                      blockIdx.y * 128, blockIdx.x * 128, smem);
}

__global__ __launch_bounds__(256) void gemm_o(const __half* __restrict__ cx,
                                              const __half* __restrict__ woh,
                                              const __half* __restrict__ wol,
                                              const float* __restrict__ bias,
                                              float* __restrict__ C) {
    extern __shared__ char smem[];
    gemm2p_body<false>(cx, woh, wol, bias, C, nullptr, nullptr,
                       blockIdx.y * 128, blockIdx.x * 128, smem);
}

// ---------------------------------------------------------------------------
// HMMA windowed flash attention (verified R8/R9 structure), bf16 hi/lo in,
// fp16 ctx out. 128 threads, 64 queries, pitch 144B, 8-tile arena, 3 CTAs/SM.
// ---------------------------------------------------------------------------
#define APITCH 144
#define ATB    (64 * APITCH)
#define ADYN   (8 * ATB)

__global__ __launch_bounds__(128, 3) void attn_mma(const __nv_bfloat16* __restrict__ Qh,
                                                   const __nv_bfloat16* __restrict__ Ql,
                                                   const __nv_bfloat16* __restrict__ Kh,
                                                   const __nv_bfloat16* __restrict__ Kl,
                                                   const __nv_bfloat16* __restrict__ Vh,
                                                   const __nv_bfloat16* __restrict__ Vl,
                                                   __half* __restrict__ cx) {
    extern __shared__ char smem[];
    const uint32_t s0 = smem_u32(smem);

    const int qb = blockIdx.x * 64;
    const int h = blockIdx.y;
    const int b = blockIdx.z;
    const int tid = threadIdx.x;
    const int warp = tid >> 5;
    const int lane = tid & 31;

    {
        const char* gQh = (const char*)Qh + (((size_t)b * SEQ + qb) * DIM + h * HDIM) * 2;
        const char* gQl = (const char*)Ql + (((size_t)b * SEQ + qb) * DIM + h * HDIM) * 2;
        for (int i = tid; i < 512; i += 128) {
            int r = i >> 3;
            int c = (i & 7) << 4;
            uint32_t dst = s0 + r * APITCH + c;
            size_t src = (size_t)r * (DIM * 2) + c;
            CP_ASYNC16(dst, gQh + src);
            CP_ASYNC16(dst + ATB, gQl + src);
        }
        CP_COMMIT();
        CP_WAIT(0);
        __syncthreads();
    }

    const int a_r = lane & 15, a_c = (lane >> 4) * 8;
    const int b_r = (lane & 7) + ((lane >> 4) & 1) * 8, b_c = ((lane >> 3) & 1) * 8;
    const int v_r = (lane & 7) + ((lane >> 3) & 1) * 8, v_c = ((lane >> 4) & 1) * 8;

    uint32_t qfh[4][4], qfl[4][4];
#pragma unroll
    for (int t = 0; t < 4; t++) {
        uint32_t off = (uint32_t)((warp * 16 + a_r) * APITCH + (t * 16 + a_c) * 2);
        ldsm_x4(qfh[t][0], qfh[t][1], qfh[t][2], qfh[t][3], s0 + off);
        ldsm_x4(qfl[t][0], qfl[t][1], qfl[t][2], qfl[t][3], s0 + ATB + off);
    }
    __syncthreads();

    int kstart = qb - (WIN - 1);
    if (kstart < 0) kstart = 0;
    kstart &= ~63;
    const int ntiles = (qb + 63 - kstart) / 64 + 1;

    auto issueKV = [&](int kt, int s) {
        const size_t base = (((size_t)b * SEQ + kt) * DIM + h * HDIM) * 2;
        const char* pKh = (const char*)Kh + base;
        const char* pKl = (const char*)Kl + base;
        const char* pVh = (const char*)Vh + base;
        const char* pVl = (const char*)Vl + base;
        uint32_t sb = s0 + s * 4 * ATB;
        for (int i = tid; i < 512; i += 128) {
            int r = i >> 3;
            int c = (i & 7) << 4;
            uint32_t dst = sb + r * APITCH + c;
            size_t src = (size_t)r * (DIM * 2) + c;
            CP_ASYNC16(dst,           pKh + src);
            CP_ASYNC16(dst + ATB,     pKl + src);
            CP_ASYNC16(dst + 2 * ATB, pVh + src);
            CP_ASYNC16(dst + 3 * ATB, pVl + src);
        }
    };

    issueKV(kstart, 0);
    CP_COMMIT();
    if (ntiles > 1) {
        issueKV(kstart + 64, 1);
        CP_COMMIT();
    }

    float m0 = -1e30f, m1 = -1e30f, l0 = 0.0f, l1 = 0.0f;
    float o[8][4];
#pragma unroll
    for (int j = 0; j < 8; j++)
#pragma unroll
        for (int r = 0; r < 4; r++) o[j][r] = 0.0f;

    const int row0 = qb + warp * 16 + (lane >> 2);
    const int row1 = row0 + 8;

    for (int it = 0; it < ntiles; ++it) {
        const int kt = kstart + it * 64;
        const int s = it & 1;
        if (it + 1 < ntiles) { CP_WAIT(1); } else { CP_WAIT(0); }
        __syncthreads();

        const uint32_t sKh = s0 + s * 4 * ATB;
        const uint32_t sKl = sKh + ATB;
        const uint32_t sVh = sKh + 2 * ATB;
        const uint32_t sVl = sKh + 3 * ATB;

        float acc[8][4];
#pragma unroll
        for (int j = 0; j < 8; j++)
#pragma unroll
            for (int r = 0; r < 4; r++) acc[j][r] = 0.0f;

#pragma unroll
        for (int t = 0; t < 4; t++) {
#pragma unroll
            for (int g = 0; g < 4; g++) {
                uint32_t off = (uint32_t)((g * 16 + b_r) * APITCH + (t * 16 + b_c) * 2);
                uint32_t kh0, kh1, kh2, kh3, kl0, kl1, kl2, kl3;
                ldsm_x4(kh0, kh1, kh2, kh3, sKh + off);
                ldsm_x4(kl0, kl1, kl2, kl3, sKl + off);
                int n0 = 2 * g, n1 = 2 * g + 1;
                mma_bf16(acc[n0][0], acc[n0][1], acc[n0][2], acc[n0][3],
                         qfh[t][0], qfh[t][1], qfh[t][2], qfh[t][3], kh0, kh1);
                mma_bf16(acc[n1][0], acc[n1][1], acc[n1][2], acc[n1][3],
                         qfh[t][0], qfh[t][1], qfh[t][2], qfh[t][3], kh2, kh3);
                mma_bf16(acc[n0][0], acc[n0][1], acc[n0][2], acc[n0][3],
                         qfh[t][0], qfh[t][1], qfh[t][2], qfh[t][3], kl0, kl1);
                mma_bf16(acc[n1][0], acc[n1][1], acc[n1][2], acc[n1][3],
                         qfh[t][0], qfh[t][1], qfh[t][2], qfh[t][3], kl2, kl3);
                mma_bf16(acc[n0][0], acc[n0][1], acc[n0][2], acc[n0][3],
                         qfl[t][0], qfl[t][1], qfl[t][2], qfl[t][3], kh0, kh1);
                mma_bf16(acc[n1][0], acc[n1][1], acc[n1][2], acc[n1][3],
                         qfl[t][0], qfl[t][1], qfl[t][2], qfl[t][3], kh2, kh3);
            }
        }

        float tmax0 = -1e30f, tmax1 = -1e30f;
#pragma unroll
        for (int j = 0; j < 8; j++) {
            int colb = kt + 8 * j + 2 * (lane & 3);
#pragma unroll
            for (int e = 0; e < 2; e++) {
                int col = colb + e;
                bool v0 = (col <= row0) && (row0 - col < WIN);
                bool v1 = (col <= row1) && (row1 - col < WIN);
                if (!v0) acc[j][e] = -1e30f;
                if (!v1) acc[j][2 + e] = -1e30f;
            }
            tmax0 = fmaxf(tmax0, fmaxf(acc[j][0], acc[j][1]));
            tmax1 = fmaxf(tmax1, fmaxf(acc[j][2], acc[j][3]));
        }
#pragma unroll
        for (int off = 1; off <= 2; off <<= 1) {
            tmax0 = fmaxf(tmax0, __shfl_xor_sync(0xffffffffu, tmax0, off));
            tmax1 = fmaxf(tmax1, __shfl_xor_sync(0xffffffffu, tmax1, off));
        }
        float mn0 = fmaxf(m0, tmax0);
        float mn1 = fmaxf(m1, tmax1);

        float rs0 = 0.0f, rs1 = 0.0f;
#pragma unroll
        for (int j = 0; j < 8; j++) {
            acc[j][0] = __expf(acc[j][0] - mn0);
            acc[j][1] = __expf(acc[j][1] - mn0);
            acc[j][2] = __expf(acc[j][2] - mn1);
            acc[j][3] = __expf(acc[j][3] - mn1);
            rs0 += acc[j][0] + acc[j][1];
            rs1 += acc[j][2] + acc[j][3];
        }
#pragma unroll
        for (int off = 1; off <= 2; off <<= 1) {
            rs0 += __shfl_xor_sync(0xffffffffu, rs0, off);
            rs1 += __shfl_xor_sync(0xffffffffu, rs1, off);
        }
        float corr0 = __expf(m0 - mn0);
        float corr1 = __expf(m1 - mn1);
        l0 = l0 * corr0 + rs0;
        l1 = l1 * corr1 + rs1;
        m0 = mn0;
        m1 = mn1;
#pragma unroll
        for (int j = 0; j < 8; j++) {
            o[j][0] *= corr0;
            o[j][1] *= corr0;
            o[j][2] *= corr1;
            o[j][3] *= corr1;
        }

#pragma unroll
        for (int t = 0; t < 4; t++) {
            uint32_t ph[4], pl[4];
            split2(acc[2 * t][0], acc[2 * t][1], ph[0], pl[0]);
            split2(acc[2 * t][2], acc[2 * t][3], ph[1], pl[1]);
            split2(acc[2 * t + 1][0], acc[2 * t + 1][1], ph[2], pl[2]);
            split2(acc[2 * t + 1][2], acc[2 * t + 1][3], ph[3], pl[3]);
#pragma unroll
            for (int g = 0; g < 4; g++) {
                uint32_t off = (uint32_t)((t * 16 + v_r) * APITCH + (g * 16 + v_c) * 2);
                uint32_t vh0, vh1, vh2, vh3, vl0, vl1, vl2, vl3;
                ldsm_x4_t(vh0, vh1, vh2, vh3, sVh + off);
                ldsm_x4_t(vl0, vl1, vl2, vl3, sVl + off);
                int n0 = 2 * g, n1 = 2 * g + 1;
                mma_bf16(o[n0][0], o[n0][1], o[n0][2], o[n0][3],
                         ph[0], ph[1], ph[2], ph[3], vh0, vh1);
                mma_bf16(o[n1][0], o[n1][1], o[n1][2], o[n1][3],
                         ph[0], ph[1], ph[2], ph[3], vh2, vh3);
                mma_bf16(o[n0][0], o[n0][1], o[n0][2], o[n0][3],
                         ph[0], ph[1], ph[2], ph[3], vl0, vl1);
                mma_bf16(o[n1][0], o[n1][1], o[n1][2], o[n1][3],
                         ph[0], ph[1], ph[2], ph[3], vl2, vl3);
                mma_bf16(o[n0][0], o[n0][1], o[n0][2], o[n0][3],
                         pl[0], pl[1], pl[2], pl[3], vh0, vh1);
                mma_bf16(o[n1][0], o[n1][1], o[n1][2], o[n1][3],
                         pl[0], pl[1], pl[2], pl[3], vh2, vh3);
            }
        }
        __syncthreads();
        if (it + 2 < ntiles) {
            issueKV(kstart + (it + 2) * 64, s);
            CP_COMMIT();
        }
    }

    float inv0 = 1.0f / l0;
    float inv1 = 1.0f / l1;
    const size_t tok0 = (size_t)b * SEQ + row0;
    const size_t tok1 = (size_t)b * SEQ + row1;
    const int colbase = h * HDIM + 2 * (lane & 3);
#pragma unroll
    for (int j = 0; j < 8; j++) {
        int col = colbase + 8 * j;
        *(uint32_t*)(cx + tok0 * DIM + col) = pack_h2(o[j][0] * inv0, o[j][1] * inv0);
        *(uint32_t*)(cx + tok1 * DIM + col) = pack_h2(o[j][2] * inv1, o[j][3] * inv1);
    }
}

// ---------------------------------------------------------------------------
extern "C" void kernel_launch(void* const* d_in, const int* in_sizes, int n_in,
                              void* d_out, int out_size) {
    (void)in_sizes; (void)n_in; (void)out_size;
    const float* X  = (const float*)d_in[0];
    const float* Wq = (const float*)d_in[1];
    const float* Wk = (const float*)d_in[2];
    const float* Wv = (const float*)d_in[3];
    const float* Wo = (const float*)d_in[4];
    const float* bo = (const float*)d_in[5];
    float* out = (float*)d_out;

    __nv_bfloat16 *qh, *ql, *kh, *kl, *vh, *vl, *xh, *xl;
    __nv_bfloat16 *wqh, *wql, *wkh, *wkl;
    __half *x16, *cx16, *wvh16, *wvl16, *woh16, *wol16;
    cudaGetSymbolAddress((void**)&qh, g_qh);
    cudaGetSymbolAddress((void**)&ql, g_ql);
    cudaGetSymbolAddress((void**)&kh, g_kh);
    cudaGetSymbolAddress((void**)&kl, g_kl);
    cudaGetSymbolAddress((void**)&vh, g_vh);
    cudaGetSymbolAddress((void**)&vl, g_vl);
    cudaGetSymbolAddress((void**)&xh, g_xh);
    cudaGetSymbolAddress((void**)&xl, g_xl);
    cudaGetSymbolAddress((void**)&x16, g_x16);
    cudaGetSymbolAddress((void**)&cx16, g_cx16);
    cudaGetSymbolAddress((void**)&wqh, g_wqh);
    cudaGetSymbolAddress((void**)&wql, g_wql);
    cudaGetSymbolAddress((void**)&wkh, g_wkh);
    cudaGetSymbolAddress((void**)&wkl, g_wkl);
    cudaGetSymbolAddress((void**)&wvh16, g_wvh16);
    cudaGetSymbolAddress((void**)&wvl16, g_wvl16);
    cudaGetSymbolAddress((void**)&woh16, g_woh16);
    cudaGetSymbolAddress((void**)&wol16, g_wol16);

    const int DYN3 = 2 * STAGEB;
    cudaFuncSetAttribute(gemm_qk, cudaFuncAttributeMaxDynamicSharedMemorySize, DYN3);
    cudaFuncSetAttribute(gemm_v,  cudaFuncAttributeMaxDynamicSharedMemorySize, H2DYN);
    cudaFuncSetAttribute(gemm_o,  cudaFuncAttributeMaxDynamicSharedMemorySize, H2DYN);
    cudaFuncSetAttribute(attn_mma, cudaFuncAttributeMaxDynamicSharedMemorySize, ADYN);

    const int nX = MROWS * DIM;
    const int nW = DIM * DIM;

    split_x<<<nX / 1024, 256>>>(X, xh, xl, x16);
    dim3 wgrid(nW / 1024, 4);
    conv_w4<<<wgrid, 256>>>(Wq, Wk, Wv, Wo,
                            wqh, wql, wkh, wkl, wvh16, wvl16, woh16, wol16);

    dim3 qk_grid(DIM / 128, MROWS / 128, 2);
    gemm_qk<<<qk_grid, 256, DYN3>>>(xh, xl, wqh, wql, wkh, wkl, qh, ql, kh, kl);

    dim3 vgrid(DIM / 128, MROWS / 128);
    gemm_v<<<vgrid, 256, H2DYN>>>(x16, wvh16, wvl16, vh, vl);

    dim3 attn_grid(SEQ / 64, NHEAD, BATCH);
    attn_mma<<<attn_grid, 128, ADYN>>>(qh, ql, kh, kl, vh, vl, cx16);

    gemm_o<<<vgrid, 256, H2DYN>>>(cx16, woh16, wol16, bo, out);
}